// round 7
// baseline (speedup 1.0000x reference)
#include <cuda_runtime.h>
#include <math.h>

#define B_    32
#define H_    8
#define E_    64
#define M_    64
#define L_    1024
#define DOUT_ 64
#define HE    512
#define M2    128

// ---------------- device scratch ----------------
__device__ float d_QfP[4][B_ * HE * M2];      // q spectrum partials (4-way usplit)
__device__ float d_KfP[4][B_ * HE * M2];
__device__ float d_KV[512 * 2 * 2048];        // kv: [(h*64+x)][c][b*64+e]
__device__ float d_WTr[8 * 64 * 64 * 64];     // wT [h][m][e][o]
__device__ float d_WTi[8 * 64 * 64 * 64];
__device__ float d_X2T[128 * 16384];          // [2*slot+c][(b*8+h)*64+o]
__device__ float2 d_sc[L_];                   // (cos, sin) LUT, fp64-accurate

// radix-8 forward twiddles [z][part(0=re,1=im)][u][128 slots]
__device__ float d_T8m[2][2][128][128];
__device__ float d_T8s[2][2][128][128];
// radix-8 meta
__device__ int d_m8v[2][128];
__device__ int d_pgA8v[2][32];
__device__ int d_pgB8v[2][32];
__device__ int d_nc8[2][128];
__device__ int d_Spad8[2];

// inverse tables (q modes, mod-4 scheme)
__device__ float d_TRr[64 * 256], d_TRi[64 * 256], d_TIr[32 * 256], d_TIi[32 * 256];
__device__ int d_slotm_q[64];
__device__ int d_pos2slot_q[64];
__device__ int d_bnd_q[2];

// ---------------- sincos LUT (fp64) ----------------------------------------
__global__ void sc_k() {
    int t = blockIdx.x * 256 + threadIdx.x;   // 0..1023
    const double C = 6.283185307179586476925286766559 / (double)L_;
    double th = C * (double)t;
    d_sc[t] = make_float2((float)cos(th), (float)sin(th));
}

// ---------------- meta for inverse ----------------------------------------
__global__ void meta_k(const int* __restrict__ iq) {
    int j = threadIdx.x;
    __shared__ int mA[64], keys[64];
    mA[j] = iq[j];
    __syncthreads();
    int m = mA[j], c = m & 3;
    int oidx = (c == 0) ? 0 : ((c == 2) ? 1 : ((c == 1) ? 2 : 3));
    keys[j] = oidx * 64 + j;
    __syncthreads();
    int key = keys[j], slot = 0;
    for (int t = 0; t < 64; t++) slot += (keys[t] < key);
    d_slotm_q[slot] = m;
    d_pos2slot_q[j] = slot;
    __syncthreads();
    if (j == 0) {
        int c0 = 0, c1 = 0, c2 = 0;
        for (int t = 0; t < 64; t++) {
            int cc = mA[t] & 3;
            c0 += (cc == 0); c1 += (cc == 1); c2 += (cc == 2);
        }
        d_bnd_q[0] = c0;
        d_bnd_q[1] = c0 + c2 + c1;
    }
}

// ---------------- meta for radix-8 forward ---------------------------------
__global__ void meta8_k(const int* __restrict__ iq, const int* __restrict__ ikv) {
    int z = blockIdx.x, j = threadIdx.x;
    __shared__ int mS[64];
    const int* ix = z ? ikv : iq;
    mS[j] = ix[j];
    __syncthreads();
    if (j == 0) {
        int cS[64], cnt[5] = {0,0,0,0,0};
        for (int t = 0; t < 64; t++) {
            int c = mS[t] & 7;
            int cp = (c <= 4) ? c : 8 - c;
            cS[t] = cp; cnt[cp]++;
        }
        int pb[5], pe[5], acc = 0;
        for (int c = 0; c < 5; c++) { pb[c] = acc; acc += (cnt[c] + 3) & ~3; pe[c] = acc; }
        d_Spad8[z] = acc;
        int posA[128];
        for (int s = 0; s < 128; s++) { d_m8v[z][s] = -1; posA[s] = -1; }
        int fill[5] = {0,0,0,0,0};
        for (int t = 0; t < 64; t++) {
            int s = pb[cS[t]] + fill[cS[t]]++;
            d_m8v[z][s] = mS[t];
            posA[s] = t;
        }
        const int pAt[5] = {0, 2, 4, 6, 1};
        const int pBt[5] = {0, 3, 5, 7, 1};
        for (int g = 0; g < 32; g++) {
            int s0 = g * 4, A = 0, Bp = 0;
            for (int c = 0; c < 5; c++)
                if (cnt[c] > 0 && s0 >= pb[c] && s0 < pe[c]) { A = pAt[c]; Bp = pBt[c]; }
            d_pgA8v[z][g] = A;
            d_pgB8v[z][g] = Bp;
        }
        for (int s = 0; s < 128; s++) d_nc8[z][s] = posA[s];
    }
}

// ---------------- radix-8 forward tables (LUT gather) ----------------------
__global__ void tables8_k() {
    int z = blockIdx.y;
    int idx = blockIdx.x * 256 + threadIdx.x;   // 0..16383
    int u = idx >> 7, s = idx & 127;
    int m = d_m8v[z][s];
    float tmr = 0.f, tsr = 0.f, tmi = 0.f, tsi = 0.f;
    if (m >= 0) {
        float2 cssn = d_sc[(m * u) & (L_ - 1)];
        int c = m & 7;
        float sg = (c <= 4) ? 1.f : -1.f;
        bool noB = (c == 0) || (c == 4);
        tmr = cssn.x;
        tsr = noB ? 0.f : (sg * cssn.y);
        tmi = -cssn.y;
        tsi = noB ? 0.f : (sg * cssn.x);
    }
    d_T8m[z][0][u][s] = tmr;
    d_T8s[z][0][u][s] = tsr;
    d_T8m[z][1][u][s] = tmi;
    d_T8s[z][1][u][s] = tsi;
}

// ---------------- inverse tables (LUT gather) -------------------------------
__global__ void tables_k() {
    int t = blockIdx.x;
    int j = threadIdx.x;
    int m = d_slotm_q[j];
    float2 cssn = d_sc[(m * t) & (L_ - 1)];
    float g = ((m == 0) || (2 * m == L_)) ? (1.0f / L_) : (2.0f / L_);
    d_TRr[j * 256 + t] =  g * cssn.x;
    d_TRi[j * 256 + t] = -g * cssn.y;
    if (j >= 32) {
        d_TIr[(j - 32) * 256 + t] = g * cssn.y;
        d_TIi[(j - 32) * 256 + t] = g * cssn.x;
    }
}

// ---------------- w transpose ----------------------------------------------
__global__ __launch_bounds__(256) void wtrans_k(const float* __restrict__ wr_g,
                                                const float* __restrict__ wi_g) {
    __shared__ float tile[32][33];
    const int ot = (blockIdx.x & 1) * 32;
    const int mt = (blockIdx.x >> 1) * 32;
    const int e  = blockIdx.y;
    const int h  = blockIdx.z;
    const int r  = threadIdx.x >> 3;
    const int c4 = (threadIdx.x & 7) * 4;

    for (int z = 0; z < 2; z++) {
        const float* src = z ? wi_g : wr_g;
        float* dst = z ? d_WTi : d_WTr;
        float4 v = *(const float4*)&src[((size_t)(h * 64 + e) * 64 + ot + r) * 64 + mt + c4];
        tile[r][c4 + 0] = v.x; tile[r][c4 + 1] = v.y;
        tile[r][c4 + 2] = v.z; tile[r][c4 + 3] = v.w;
        __syncthreads();
        float4 o;
        o.x = tile[c4 + 0][r]; o.y = tile[c4 + 1][r];
        o.z = tile[c4 + 2][r]; o.w = tile[c4 + 3][r];
        *(float4*)&dst[((size_t)(h * 64 + mt + r) * 64 + e) * 64 + ot + c4] = o;
        __syncthreads();
    }
}

// ---------------- forward: merged radix-8 folded partial DFT ---------------
#define PLPAD 68
#define PLBUF (8 * 8 * PLPAD)
__global__ __launch_bounds__(128, 4) void dft8m_k(const float* __restrict__ qg,
                                                  const float* __restrict__ kg) {
    const int bx   = blockIdx.x;
    const int tile = bx & 1;
    const int us   = (bx >> 1) & 3;
    const int heT  = bx >> 3;
    const int b    = blockIdx.y;
    const int zin  = blockIdx.z;
    if (tile * 64 >= d_Spad8[zin]) return;

    extern __shared__ float sm[];
    float* PL = sm;                  // [2][8u][8pl][68]
    float* TW = sm + 2 * PLBUF;      // [2][8u][4][64]

    const float* __restrict__ x = zin ? kg : qg;
    float* outp = zin ? d_KfP[us] : d_QfP[us];
    const int he0 = heT * 64;
    const int tid = threadIdx.x;
    const int g   = tid & 15;
    const int cx  = g * 4;
    const int ry  = (tid >> 4) * 8;
    const int pgA = d_pgA8v[zin][tile * 16 + g];
    const int pgB = d_pgB8v[zin][tile * 16 + g];
    const float* xb = x + (size_t)b * (L_ * HE) + he0;

    float accR[8][4], accI[8][4];
    #pragma unroll
    for (int i = 0; i < 8; i++)
        #pragma unroll
        for (int j = 0; j < 4; j++) { accR[i][j] = 0.f; accI[i][j] = 0.f; }

    auto load = [&](int ks, int buf) {
        const int u0 = us * 32 + ks * 8;
        float* plb = PL + buf * PLBUF;
        {
            const int ul = tid >> 4;
            const int c4 = (tid & 15) * 4;
            const float* p = xb + (size_t)(u0 + ul) * HE + c4;
            float4 xs[8];
            #pragma unroll
            for (int pp = 0; pp < 8; pp++)
                xs[pp] = *(const float4*)(p + (size_t)pp * 128 * HE);
            float4 pl8[8];
            const float KK = 0.70710678118654752440f;
            #pragma unroll
            for (int q = 0; q < 4; q++) {
                float x0 = (&xs[0].x)[q], x1 = (&xs[1].x)[q], x2 = (&xs[2].x)[q], x3 = (&xs[3].x)[q];
                float x4 = (&xs[4].x)[q], x5 = (&xs[5].x)[q], x6 = (&xs[6].x)[q], x7 = (&xs[7].x)[q];
                float e0 = x0 + x4, e1 = x1 + x5, e2 = x2 + x6, e3 = x3 + x7;
                float o0 = x0 - x4, o1 = x1 - x5, o2 = x2 - x6, o3 = x3 - x7;
                float g0 = e0 + e2, g1 = e1 + e3;
                float t1 = o1 - o3, t2 = o1 + o3;
                float kt1 = KK * t1, kt2 = KK * t2;
                (&pl8[0].x)[q] = g0 + g1;
                (&pl8[1].x)[q] = g0 - g1;
                (&pl8[2].x)[q] = o0 + kt1;
                (&pl8[3].x)[q] = -kt2 - o2;
                (&pl8[4].x)[q] = e0 - e2;
                (&pl8[5].x)[q] = e3 - e1;
                (&pl8[6].x)[q] = o0 - kt1;
                (&pl8[7].x)[q] = o2 - kt2;
            }
            #pragma unroll
            for (int pl = 0; pl < 8; pl++)
                *(float4*)&plb[(ul * 8 + pl) * PLPAD + c4] = pl8[pl];
        }
        float* twb = TW + buf * 2048;
        #pragma unroll
        for (int r = 0; r < 4; r++) {
            int f = tid + 128 * r;
            int uu  = f >> 6;
            int wh  = (f >> 4) & 3;
            int c4t = (f & 15) * 4;
            const float* srcT;
            if (wh == 0)      srcT = &d_T8m[zin][0][u0 + uu][tile * 64];
            else if (wh == 1) srcT = &d_T8s[zin][0][u0 + uu][tile * 64];
            else if (wh == 2) srcT = &d_T8m[zin][1][u0 + uu][tile * 64];
            else              srcT = &d_T8s[zin][1][u0 + uu][tile * 64];
            *(float4*)&twb[(uu * 4 + wh) * 64 + c4t] = *(const float4*)(srcT + c4t);
        }
    };

    load(0, 0);
    __syncthreads();
    #pragma unroll 1
    for (int ks = 0; ks < 4; ks++) {
        int buf = ks & 1;
        if (ks + 1 < 4) load(ks + 1, buf ^ 1);
        float* plb = PL + buf * PLBUF;
        float* twb = TW + buf * 2048;
        #pragma unroll
        for (int u = 0; u < 8; u++) {
            float av[8], bw[8], tmr[4], tsr[4], tmi[4], tsi[4];
            *(float4*)&av[0] = *(float4*)&plb[(u * 8 + pgA) * PLPAD + ry];
            *(float4*)&av[4] = *(float4*)&plb[(u * 8 + pgA) * PLPAD + ry + 4];
            *(float4*)&bw[0] = *(float4*)&plb[(u * 8 + pgB) * PLPAD + ry];
            *(float4*)&bw[4] = *(float4*)&plb[(u * 8 + pgB) * PLPAD + ry + 4];
            *(float4*)&tmr[0] = *(float4*)&twb[(u * 4 + 0) * 64 + cx];
            *(float4*)&tsr[0] = *(float4*)&twb[(u * 4 + 1) * 64 + cx];
            *(float4*)&tmi[0] = *(float4*)&twb[(u * 4 + 2) * 64 + cx];
            *(float4*)&tsi[0] = *(float4*)&twb[(u * 4 + 3) * 64 + cx];
            #pragma unroll
            for (int i = 0; i < 8; i++)
                #pragma unroll
                for (int j = 0; j < 4; j++) {
                    accR[i][j] += av[i] * tmr[j] + bw[i] * tsr[j];
                    accI[i][j] += av[i] * tmi[j] + bw[i] * tsi[j];
                }
        }
        __syncthreads();
    }

    int nc[4];
    #pragma unroll
    for (int j = 0; j < 4; j++) nc[j] = d_nc8[zin][tile * 64 + cx + j];
    float* dst = outp + ((size_t)b * HE + he0 + ry) * M2;
    #pragma unroll
    for (int j = 0; j < 4; j++) {
        if (nc[j] >= 0) {
            #pragma unroll
            for (int i = 0; i < 8; i++) {
                dst[(size_t)i * M2 + nc[j]]      = accR[i][j];
                dst[(size_t)i * M2 + 64 + nc[j]] = accI[i][j];
            }
        }
    }
}

// ---------------- stage2+3 split by x-half ---------------------------------
// grid (H, B, 2); block 128 thr; smem: Ks [64][128] 32KB, Qs [64][64] 16KB
// qk aliases Qs after sync.
__global__ __launch_bounds__(128) void stage23_k() {
    extern __shared__ float sm[];
    float* Ks  = sm;            // [64][128]
    float* Qs  = sm + 8192;     // [64][64]: cols 0..31 re(x-half), 32..63 im
    float* qkr = sm + 8192;     // alias [y][32]
    float* qki = sm + 10240;    // alias [y][32]

    const int h = blockIdx.x, b = blockIdx.y, xh = blockIdx.z;
    const int xbase = xh * 32;
    const int tid = threadIdx.x;

    const size_t off4 = (((size_t)b * HE + h * E_) * M2) / 4;
    for (int i = tid; i < 2048; i += 128) {
        float4 c0 = ((const float4*)d_KfP[0])[off4 + i];
        float4 c1 = ((const float4*)d_KfP[1])[off4 + i];
        float4 c2 = ((const float4*)d_KfP[2])[off4 + i];
        float4 c3 = ((const float4*)d_KfP[3])[off4 + i];
        ((float4*)Ks)[i] = make_float4(c0.x + c1.x + c2.x + c3.x,
                                       c0.y + c1.y + c2.y + c3.y,
                                       c0.z + c1.z + c2.z + c3.z,
                                       c0.w + c1.w + c2.w + c3.w);
    }
    for (int i = tid; i < 1024; i += 128) {
        int e = i >> 4, j = i & 15;
        int src4 = (j < 8) ? (xbase / 4 + j) : (16 + xbase / 4 + (j - 8));
        float4 a0 = ((const float4*)d_QfP[0])[off4 + e * 32 + src4];
        float4 a1 = ((const float4*)d_QfP[1])[off4 + e * 32 + src4];
        float4 a2 = ((const float4*)d_QfP[2])[off4 + e * 32 + src4];
        float4 a3 = ((const float4*)d_QfP[3])[off4 + e * 32 + src4];
        ((float4*)Qs)[e * 16 + j] = make_float4(a0.x + a1.x + a2.x + a3.x,
                                                a0.y + a1.y + a2.y + a3.y,
                                                a0.z + a1.z + a2.z + a3.z,
                                                a0.w + a1.w + a2.w + a3.w);
    }
    __syncthreads();

    const int x0 = (tid & 7) * 4;      // local x (0..28)
    {
        int y0 = (tid >> 3) * 4;       // 0..60
        float ar[4][4], ai[4][4];
        #pragma unroll
        for (int yy = 0; yy < 4; yy++)
            #pragma unroll
            for (int xx = 0; xx < 4; xx++) { ar[yy][xx] = 0.f; ai[yy][xx] = 0.f; }
        #pragma unroll 4
        for (int e = 0; e < 64; e++) {
            float4 q4r = *(float4*)&Qs[e * 64 + x0];
            float4 q4i = *(float4*)&Qs[e * 64 + 32 + x0];
            float4 k4r = *(float4*)&Ks[e * 128 + y0];
            float4 k4i = *(float4*)&Ks[e * 128 + 64 + y0];
            float qrv[4] = {q4r.x,q4r.y,q4r.z,q4r.w};
            float qiv[4] = {q4i.x,q4i.y,q4i.z,q4i.w};
            float krv[4] = {k4r.x,k4r.y,k4r.z,k4r.w};
            float kiv[4] = {k4i.x,k4i.y,k4i.z,k4i.w};
            #pragma unroll
            for (int yy = 0; yy < 4; yy++)
                #pragma unroll
                for (int xx = 0; xx < 4; xx++) {
                    ar[yy][xx] += qrv[xx]*krv[yy] - qiv[xx]*kiv[yy];
                    ai[yy][xx] += qrv[xx]*kiv[yy] + qiv[xx]*krv[yy];
                }
        }
        __syncthreads();   // Qs reads done before aliased qk write
        #pragma unroll
        for (int yy = 0; yy < 4; yy++)
            #pragma unroll
            for (int xx = 0; xx < 4; xx++) {
                qkr[(y0 + yy) * 32 + x0 + xx] = tanhf(ar[yy][xx]);
                qki[(y0 + yy) * 32 + x0 + xx] = tanhf(ai[yy][xx]);
            }
    }
    __syncthreads();

    {
        int e0 = (tid >> 3) * 4;       // 0..60
        float cr[4][4], ci[4][4];
        #pragma unroll
        for (int ee = 0; ee < 4; ee++)
            #pragma unroll
            for (int xx = 0; xx < 4; xx++) { cr[ee][xx] = 0.f; ci[ee][xx] = 0.f; }
        #pragma unroll 4
        for (int y = 0; y < 64; y++) {
            float4 q4r = *(float4*)&qkr[y * 32 + x0];
            float4 q4i = *(float4*)&qki[y * 32 + x0];
            float qrv[4] = {q4r.x,q4r.y,q4r.z,q4r.w};
            float qiv[4] = {q4i.x,q4i.y,q4i.z,q4i.w};
            float krv[4], kiv[4];
            #pragma unroll
            for (int ee = 0; ee < 4; ee++) {
                krv[ee] = Ks[(e0 + ee) * 128 + y];
                kiv[ee] = Ks[(e0 + ee) * 128 + 64 + y];
            }
            #pragma unroll
            for (int ee = 0; ee < 4; ee++)
                #pragma unroll
                for (int xx = 0; xx < 4; xx++) {
                    cr[ee][xx] += qrv[xx]*krv[ee] - qiv[xx]*kiv[ee];
                    ci[ee][xx] += qrv[xx]*kiv[ee] + qiv[xx]*krv[ee];
                }
        }
        #pragma unroll
        for (int xx = 0; xx < 4; xx++) {
            size_t base = ((size_t)(h * 64 + xbase + x0 + xx) * 2) * 2048 + b * 64 + e0;
            *(float4*)&d_KV[base]        = make_float4(cr[0][xx], cr[1][xx], cr[2][xx], cr[3][xx]);
            *(float4*)&d_KV[base + 2048] = make_float4(ci[0][xx], ci[1][xx], ci[2][xx], ci[3][xx]);
        }
    }
}

// ---------------- stage4: per-(h,mode) pointwise complex GEMM --------------
__global__ __launch_bounds__(128) void xw_k() {
    extern __shared__ float sm[];
    float* kvS = sm;         // [e][c][b]
    float* wS  = sm + 4096;  // [e][c][o]
    const int x = blockIdx.x, h = blockIdx.y;
    const int tid = threadIdx.x;

    {
        const float4* kb = (const float4*)(d_KV + ((size_t)(h * 64 + x) * 2) * 2048);
        #pragma unroll
        for (int r = 0; r < 8; r++) {
            int idx4 = tid + 128 * r;
            float4 v = kb[idx4];
            int e4 = idx4 & 15, bb = (idx4 >> 4) & 31, c = idx4 >> 9;
            #pragma unroll
            for (int j = 0; j < 4; j++)
                kvS[((e4 * 4 + j) * 2 + c) * 32 + bb] = (&v.x)[j];
        }
        const float4* wrb = (const float4*)(d_WTr + (size_t)(h * 64 + x) * 4096);
        const float4* wib = (const float4*)(d_WTi + (size_t)(h * 64 + x) * 4096);
        #pragma unroll
        for (int r = 0; r < 8; r++) {
            int idx4 = tid + 128 * r;
            int e = idx4 >> 4, o4 = idx4 & 15;
            *(float4*)&wS[(e * 2 + 0) * 64 + o4 * 4] = wrb[idx4];
            *(float4*)&wS[(e * 2 + 1) * 64 + o4 * 4] = wib[idx4];
        }
    }
    __syncthreads();

    const int b0 = (tid >> 4) * 4;
    const int o0 = (tid & 15) * 4;
    float cr[4][4], ci[4][4];
    #pragma unroll
    for (int i = 0; i < 4; i++)
        #pragma unroll
        for (int j = 0; j < 4; j++) { cr[i][j] = 0.f; ci[i][j] = 0.f; }

    #pragma unroll 4
    for (int e = 0; e < 64; e++) {
        float4 kr4 = *(float4*)&kvS[(e * 2 + 0) * 32 + b0];
        float4 ki4 = *(float4*)&kvS[(e * 2 + 1) * 32 + b0];
        float4 wr4 = *(float4*)&wS[(e * 2 + 0) * 64 + o0];
        float4 wi4 = *(float4*)&wS[(e * 2 + 1) * 64 + o0];
        float kr[4] = {kr4.x,kr4.y,kr4.z,kr4.w};
        float ki[4] = {ki4.x,ki4.y,ki4.z,ki4.w};
        float wr[4] = {wr4.x,wr4.y,wr4.z,wr4.w};
        float wi[4] = {wi4.x,wi4.y,wi4.z,wi4.w};
        #pragma unroll
        for (int i = 0; i < 4; i++)
            #pragma unroll
            for (int j = 0; j < 4; j++) {
                cr[i][j] += kr[i]*wr[j] - ki[i]*wi[j];
                ci[i][j] += kr[i]*wi[j] + ki[i]*wr[j];
            }
    }
    __syncthreads();

    const float S = 1.0f / 262144.0f;
    #pragma unroll
    for (int i = 0; i < 4; i++) {
        *(float4*)&wS[(0 * 32 + b0 + i) * 64 + o0] =
            make_float4(cr[i][0]*S, cr[i][1]*S, cr[i][2]*S, cr[i][3]*S);
        *(float4*)&wS[(1 * 32 + b0 + i) * 64 + o0] =
            make_float4(ci[i][0]*S, ci[i][1]*S, ci[i][2]*S, ci[i][3]*S);
    }
    __syncthreads();

    int slot = d_pos2slot_q[x];
    #pragma unroll
    for (int r = 0; r < 8; r++) {
        int idx4 = tid + 128 * r;
        int c = idx4 >> 9, bb = (idx4 >> 4) & 31, o4 = idx4 & 15;
        *(float4*)&d_X2T[(size_t)(2 * slot + c) * 16384 + (bb * 8 + h) * 64 + o4 * 4] =
            ((float4*)wS)[idx4];
    }
}

// ---------------- inverse: folded irfft (radix-4) ---------------------------
__global__ __launch_bounds__(256) void inv_fold_k(float* __restrict__ outp) {
    extern __shared__ float sm[];
    float* Ys = sm;
    float* Rr = sm + 8192;
    float* Ri = sm + 12288;
    float* Ir = sm + 16384;
    float* Ii = sm + 18432;
    const int u0 = blockIdx.x * 64;
    const int r0 = blockIdx.y * 64;
    const int tid = threadIdx.x;

    {
        for (int i = tid; i < 2048; i += 256) {
            int p = i >> 4, r4 = (i & 15) * 4;
            float4 v = *(const float4*)&d_X2T[(size_t)p * 16384 + r0 + r4];
            Ys[(r4 + 0) * 128 + p] = v.x;
            Ys[(r4 + 1) * 128 + p] = v.y;
            Ys[(r4 + 2) * 128 + p] = v.z;
            Ys[(r4 + 3) * 128 + p] = v.w;
        }
        for (int i = tid; i < 1024; i += 256) {
            int s = i >> 4, c4 = (i & 15) * 4;
            *(float4*)&Rr[s * 64 + c4] = *(const float4*)&d_TRr[s * 256 + u0 + c4];
            *(float4*)&Ri[s * 64 + c4] = *(const float4*)&d_TRi[s * 256 + u0 + c4];
        }
        for (int i = tid; i < 512; i += 256) {
            int s = i >> 4, c4 = (i & 15) * 4;
            *(float4*)&Ir[s * 64 + c4] = *(const float4*)&d_TIr[s * 256 + u0 + c4];
            *(float4*)&Ii[s * 64 + c4] = *(const float4*)&d_TIi[s * 256 + u0 + c4];
        }
    }
    __syncthreads();

    const int rr = (tid >> 4) * 4;
    const int uu = (tid & 15) * 4;
    float R0[4][4] = {}, R2[4][4] = {}, R1[4][4] = {}, I1[4][4] = {}, R3[4][4] = {}, I3[4][4] = {};

    const int n0 = d_bnd_q[0], n1 = d_bnd_q[1];

#define ACC_R(S, AR) { \
    float4 c4v = *(float4*)&Rr[(S) * 64 + uu]; \
    float4 d4v = *(float4*)&Ri[(S) * 64 + uu]; \
    float cv[4] = {c4v.x,c4v.y,c4v.z,c4v.w}; \
    float dv[4] = {d4v.x,d4v.y,d4v.z,d4v.w}; \
    _Pragma("unroll") \
    for (int r_ = 0; r_ < 4; r_++) { \
        float2 y = *(float2*)&Ys[(rr + r_) * 128 + 2 * (S)]; \
        _Pragma("unroll") \
        for (int u_ = 0; u_ < 4; u_++) AR[r_][u_] += y.x * cv[u_] + y.y * dv[u_]; \
    } }

#define ACC_RI(S, AR, AI) { \
    float4 c4v = *(float4*)&Rr[(S) * 64 + uu]; \
    float4 d4v = *(float4*)&Ri[(S) * 64 + uu]; \
    float4 e4v = *(float4*)&Ir[((S) - 32) * 64 + uu]; \
    float4 f4v = *(float4*)&Ii[((S) - 32) * 64 + uu]; \
    float cv[4] = {c4v.x,c4v.y,c4v.z,c4v.w}; \
    float dv[4] = {d4v.x,d4v.y,d4v.z,d4v.w}; \
    float ev[4] = {e4v.x,e4v.y,e4v.z,e4v.w}; \
    float fv[4] = {f4v.x,f4v.y,f4v.z,f4v.w}; \
    _Pragma("unroll") \
    for (int r_ = 0; r_ < 4; r_++) { \
        float2 y = *(float2*)&Ys[(rr + r_) * 128 + 2 * (S)]; \
        _Pragma("unroll") \
        for (int u_ = 0; u_ < 4; u_++) { \
            AR[r_][u_] += y.x * cv[u_] + y.y * dv[u_]; \
            AI[r_][u_] += y.x * ev[u_] + y.y * fv[u_]; \
        } \
    } }

    for (int s = 0; s < n0; s++)  ACC_R(s, R0);
    for (int s = n0; s < 32; s++) ACC_R(s, R2);
    for (int s = 32; s < n1; s++) ACC_RI(s, R1, I1);
    for (int s = n1; s < 64; s++) ACC_RI(s, R3, I3);

#undef ACC_R
#undef ACC_RI

    #pragma unroll
    for (int r_ = 0; r_ < 4; r_++) {
        float o0[4], o1[4], o2[4], o3[4];
        #pragma unroll
        for (int u_ = 0; u_ < 4; u_++) {
            float rp = R0[r_][u_] + R2[r_][u_];
            float rm = R0[r_][u_] - R2[r_][u_];
            o0[u_] = rp + R1[r_][u_] + R3[r_][u_];
            o1[u_] = rm - I1[r_][u_] + I3[r_][u_];
            o2[u_] = rp - R1[r_][u_] - R3[r_][u_];
            o3[u_] = rm + I1[r_][u_] - I3[r_][u_];
        }
        float* dst = outp + (size_t)(r0 + rr + r_) * L_ + u0 + uu;
        *(float4*)(dst + 0)   = make_float4(o0[0], o0[1], o0[2], o0[3]);
        *(float4*)(dst + 256) = make_float4(o1[0], o1[1], o1[2], o1[3]);
        *(float4*)(dst + 512) = make_float4(o2[0], o2[1], o2[2], o2[3]);
        *(float4*)(dst + 768) = make_float4(o3[0], o3[1], o3[2], o3[3]);
    }
}

// ---------------- launch ---------------------------------------------------
extern "C" void kernel_launch(void* const* d_in, const int* in_sizes, int n_in,
                              void* d_out, int out_size) {
    const float* q   = (const float*)d_in[0];
    const float* k   = (const float*)d_in[1];
    const float* wr  = (const float*)d_in[4];
    const float* wi  = (const float*)d_in[5];
    const int*   iq  = (const int*)d_in[6];
    const int*   ikv = (const int*)d_in[7];
    float* out = (float*)d_out;

    sc_k<<<4, 256>>>();
    meta_k<<<1, 64>>>(iq);
    meta8_k<<<2, 64>>>(iq, ikv);
    tables_k<<<256, 64>>>();
    tables8_k<<<dim3(64, 2), 256>>>();
    wtrans_k<<<dim3(4, 64, 8), 256>>>(wr, wi);
    cudaFuncSetAttribute(dft8m_k, cudaFuncAttributeMaxDynamicSharedMemorySize, 51200);
    dft8m_k<<<dim3(64, B_, 2), 128, 51200>>>(q, k);
    cudaFuncSetAttribute(stage23_k, cudaFuncAttributeMaxDynamicSharedMemorySize, 49152);
    stage23_k<<<dim3(H_, B_, 2), 128, 49152>>>();
    cudaFuncSetAttribute(xw_k, cudaFuncAttributeMaxDynamicSharedMemorySize, 49152);
    xw_k<<<dim3(64, 8), 128, 49152>>>();
    cudaFuncSetAttribute(inv_fold_k, cudaFuncAttributeMaxDynamicSharedMemorySize, 81920);
    inv_fold_k<<<dim3(4, 256), 256, 81920>>>(out);
}

// round 8
// speedup vs baseline: 1.0251x; 1.0251x over previous
#include <cuda_runtime.h>
#include <math.h>

#define B_    32
#define H_    8
#define E_    64
#define M_    64
#define L_    1024
#define DOUT_ 64
#define HE    512
#define M2    128

// ---------------- device scratch ----------------
__device__ float d_QfP[4][B_ * HE * M2];      // q spectrum partials (4-way usplit)
__device__ float d_KfP[4][B_ * HE * M2];
__device__ float d_KV[512 * 2 * 2048];        // kv: [(h*64+x)][c][b*64+e]
__device__ float d_WTr[8 * 64 * 64 * 64];     // wT [h][m][e][o]
__device__ float d_WTi[8 * 64 * 64 * 64];
__device__ float d_X2T[128 * 16384];          // [2*slot+c][(b*8+h)*64+o]
__device__ float2 d_sc[L_];                   // (cos, sin) LUT, fp64-accurate

// radix-8 forward twiddles [z][part(0=re,1=im)][u][128 slots]
__device__ float d_T8m[2][2][128][128];
__device__ float d_T8s[2][2][128][128];
// radix-8 meta
__device__ int d_m8v[2][128];
__device__ int d_pgA8v[2][32];
__device__ int d_pgB8v[2][32];
__device__ int d_nc8[2][128];
__device__ int d_Spad8[2];

// inverse tables (q modes, mod-4 scheme)
__device__ float d_TRr[64 * 256], d_TRi[64 * 256], d_TIr[32 * 256], d_TIi[32 * 256];
__device__ int d_slotm_q[64];
__device__ int d_pos2slot_q[64];
__device__ int d_bnd_q[2];

// ---------------- sincos LUT (fp64) ----------------------------------------
__global__ void sc_k() {
    int t = blockIdx.x * 256 + threadIdx.x;   // 0..1023
    const double C = 6.283185307179586476925286766559 / (double)L_;
    double th = C * (double)t;
    d_sc[t] = make_float2((float)cos(th), (float)sin(th));
}

// ---------------- meta for inverse ----------------------------------------
__global__ void meta_k(const int* __restrict__ iq) {
    int j = threadIdx.x;
    __shared__ int mA[64], keys[64];
    mA[j] = iq[j];
    __syncthreads();
    int m = mA[j], c = m & 3;
    int oidx = (c == 0) ? 0 : ((c == 2) ? 1 : ((c == 1) ? 2 : 3));
    keys[j] = oidx * 64 + j;
    __syncthreads();
    int key = keys[j], slot = 0;
    for (int t = 0; t < 64; t++) slot += (keys[t] < key);
    d_slotm_q[slot] = m;
    d_pos2slot_q[j] = slot;
    __syncthreads();
    if (j == 0) {
        int c0 = 0, c1 = 0, c2 = 0;
        for (int t = 0; t < 64; t++) {
            int cc = mA[t] & 3;
            c0 += (cc == 0); c1 += (cc == 1); c2 += (cc == 2);
        }
        d_bnd_q[0] = c0;
        d_bnd_q[1] = c0 + c2 + c1;
    }
}

// ---------------- meta for radix-8 forward ---------------------------------
__global__ void meta8_k(const int* __restrict__ iq, const int* __restrict__ ikv) {
    int z = blockIdx.x, j = threadIdx.x;
    __shared__ int mS[64];
    const int* ix = z ? ikv : iq;
    mS[j] = ix[j];
    __syncthreads();
    if (j == 0) {
        int cS[64], cnt[5] = {0,0,0,0,0};
        for (int t = 0; t < 64; t++) {
            int c = mS[t] & 7;
            int cp = (c <= 4) ? c : 8 - c;
            cS[t] = cp; cnt[cp]++;
        }
        int pb[5], pe[5], acc = 0;
        for (int c = 0; c < 5; c++) { pb[c] = acc; acc += (cnt[c] + 3) & ~3; pe[c] = acc; }
        d_Spad8[z] = acc;
        int posA[128];
        for (int s = 0; s < 128; s++) { d_m8v[z][s] = -1; posA[s] = -1; }
        int fill[5] = {0,0,0,0,0};
        for (int t = 0; t < 64; t++) {
            int s = pb[cS[t]] + fill[cS[t]]++;
            d_m8v[z][s] = mS[t];
            posA[s] = t;
        }
        const int pAt[5] = {0, 2, 4, 6, 1};
        const int pBt[5] = {0, 3, 5, 7, 1};
        for (int g = 0; g < 32; g++) {
            int s0 = g * 4, A = 0, Bp = 0;
            for (int c = 0; c < 5; c++)
                if (cnt[c] > 0 && s0 >= pb[c] && s0 < pe[c]) { A = pAt[c]; Bp = pBt[c]; }
            d_pgA8v[z][g] = A;
            d_pgB8v[z][g] = Bp;
        }
        for (int s = 0; s < 128; s++) d_nc8[z][s] = posA[s];
    }
}

// ---------------- radix-8 forward tables (LUT gather) ----------------------
__global__ void tables8_k() {
    int z = blockIdx.y;
    int idx = blockIdx.x * 256 + threadIdx.x;   // 0..16383
    int u = idx >> 7, s = idx & 127;
    int m = d_m8v[z][s];
    float tmr = 0.f, tsr = 0.f, tmi = 0.f, tsi = 0.f;
    if (m >= 0) {
        float2 cssn = d_sc[(m * u) & (L_ - 1)];
        int c = m & 7;
        float sg = (c <= 4) ? 1.f : -1.f;
        bool noB = (c == 0) || (c == 4);
        tmr = cssn.x;
        tsr = noB ? 0.f : (sg * cssn.y);
        tmi = -cssn.y;
        tsi = noB ? 0.f : (sg * cssn.x);
    }
    d_T8m[z][0][u][s] = tmr;
    d_T8s[z][0][u][s] = tsr;
    d_T8m[z][1][u][s] = tmi;
    d_T8s[z][1][u][s] = tsi;
}

// ---------------- inverse tables (LUT gather, t-contiguous) -----------------
__global__ void tables_k() {
    int j = blockIdx.x;     // slot 0..63
    int t = threadIdx.x;    // 0..255
    int m = d_slotm_q[j];
    float2 cssn = d_sc[(m * t) & (L_ - 1)];
    float g = ((m == 0) || (2 * m == L_)) ? (1.0f / L_) : (2.0f / L_);
    d_TRr[j * 256 + t] =  g * cssn.x;
    d_TRi[j * 256 + t] = -g * cssn.y;
    if (j >= 32) {
        d_TIr[(j - 32) * 256 + t] = g * cssn.y;
        d_TIi[(j - 32) * 256 + t] = g * cssn.x;
    }
}

// ---------------- w transpose ----------------------------------------------
__global__ __launch_bounds__(256) void wtrans_k(const float* __restrict__ wr_g,
                                                const float* __restrict__ wi_g) {
    __shared__ float tile[32][33];
    const int ot = (blockIdx.x & 1) * 32;
    const int mt = (blockIdx.x >> 1) * 32;
    const int e  = blockIdx.y;
    const int h  = blockIdx.z;
    const int r  = threadIdx.x >> 3;
    const int c4 = (threadIdx.x & 7) * 4;

    for (int z = 0; z < 2; z++) {
        const float* src = z ? wi_g : wr_g;
        float* dst = z ? d_WTi : d_WTr;
        float4 v = *(const float4*)&src[((size_t)(h * 64 + e) * 64 + ot + r) * 64 + mt + c4];
        tile[r][c4 + 0] = v.x; tile[r][c4 + 1] = v.y;
        tile[r][c4 + 2] = v.z; tile[r][c4 + 3] = v.w;
        __syncthreads();
        float4 o;
        o.x = tile[c4 + 0][r]; o.y = tile[c4 + 1][r];
        o.z = tile[c4 + 2][r]; o.w = tile[c4 + 3][r];
        *(float4*)&dst[((size_t)(h * 64 + mt + r) * 64 + e) * 64 + ot + c4] = o;
        __syncthreads();
    }
}

// ---------------- forward: merged radix-8 folded partial DFT ---------------
#define PLPAD 68
#define PLBUF (8 * 8 * PLPAD)
__global__ __launch_bounds__(128, 4) void dft8m_k(const float* __restrict__ qg,
                                                  const float* __restrict__ kg) {
    const int bx   = blockIdx.x;
    const int tile = bx & 1;
    const int us   = (bx >> 1) & 3;
    const int heT  = bx >> 3;
    const int b    = blockIdx.y;
    const int zin  = blockIdx.z;
    if (tile * 64 >= d_Spad8[zin]) return;

    extern __shared__ float sm[];
    float* PL = sm;                  // [2][8u][8pl][68]
    float* TW = sm + 2 * PLBUF;      // [2][8u][4][64]

    const float* __restrict__ x = zin ? kg : qg;
    float* outp = zin ? d_KfP[us] : d_QfP[us];
    const int he0 = heT * 64;
    const int tid = threadIdx.x;
    const int g   = tid & 15;
    const int cx  = g * 4;
    const int ry  = (tid >> 4) * 8;
    const int pgA = d_pgA8v[zin][tile * 16 + g];
    const int pgB = d_pgB8v[zin][tile * 16 + g];
    const float* xb = x + (size_t)b * (L_ * HE) + he0;

    float accR[8][4], accI[8][4];
    #pragma unroll
    for (int i = 0; i < 8; i++)
        #pragma unroll
        for (int j = 0; j < 4; j++) { accR[i][j] = 0.f; accI[i][j] = 0.f; }

    auto load = [&](int ks, int buf) {
        const int u0 = us * 32 + ks * 8;
        float* plb = PL + buf * PLBUF;
        {
            const int ul = tid >> 4;
            const int c4 = (tid & 15) * 4;
            const float* p = xb + (size_t)(u0 + ul) * HE + c4;
            float4 xs[8];
            #pragma unroll
            for (int pp = 0; pp < 8; pp++)
                xs[pp] = *(const float4*)(p + (size_t)pp * 128 * HE);
            float4 pl8[8];
            const float KK = 0.70710678118654752440f;
            #pragma unroll
            for (int q = 0; q < 4; q++) {
                float x0 = (&xs[0].x)[q], x1 = (&xs[1].x)[q], x2 = (&xs[2].x)[q], x3 = (&xs[3].x)[q];
                float x4 = (&xs[4].x)[q], x5 = (&xs[5].x)[q], x6 = (&xs[6].x)[q], x7 = (&xs[7].x)[q];
                float e0 = x0 + x4, e1 = x1 + x5, e2 = x2 + x6, e3 = x3 + x7;
                float o0 = x0 - x4, o1 = x1 - x5, o2 = x2 - x6, o3 = x3 - x7;
                float g0 = e0 + e2, g1 = e1 + e3;
                float t1 = o1 - o3, t2 = o1 + o3;
                float kt1 = KK * t1, kt2 = KK * t2;
                (&pl8[0].x)[q] = g0 + g1;
                (&pl8[1].x)[q] = g0 - g1;
                (&pl8[2].x)[q] = o0 + kt1;
                (&pl8[3].x)[q] = -kt2 - o2;
                (&pl8[4].x)[q] = e0 - e2;
                (&pl8[5].x)[q] = e3 - e1;
                (&pl8[6].x)[q] = o0 - kt1;
                (&pl8[7].x)[q] = o2 - kt2;
            }
            #pragma unroll
            for (int pl = 0; pl < 8; pl++)
                *(float4*)&plb[(ul * 8 + pl) * PLPAD + c4] = pl8[pl];
        }
        float* twb = TW + buf * 2048;
        #pragma unroll
        for (int r = 0; r < 4; r++) {
            int f = tid + 128 * r;
            int uu  = f >> 6;
            int wh  = (f >> 4) & 3;
            int c4t = (f & 15) * 4;
            const float* srcT;
            if (wh == 0)      srcT = &d_T8m[zin][0][u0 + uu][tile * 64];
            else if (wh == 1) srcT = &d_T8s[zin][0][u0 + uu][tile * 64];
            else if (wh == 2) srcT = &d_T8m[zin][1][u0 + uu][tile * 64];
            else              srcT = &d_T8s[zin][1][u0 + uu][tile * 64];
            *(float4*)&twb[(uu * 4 + wh) * 64 + c4t] = *(const float4*)(srcT + c4t);
        }
    };

    load(0, 0);
    __syncthreads();
    #pragma unroll 1
    for (int ks = 0; ks < 4; ks++) {
        int buf = ks & 1;
        if (ks + 1 < 4) load(ks + 1, buf ^ 1);
        float* plb = PL + buf * PLBUF;
        float* twb = TW + buf * 2048;
        #pragma unroll
        for (int u = 0; u < 8; u++) {
            float av[8], bw[8], tmr[4], tsr[4], tmi[4], tsi[4];
            *(float4*)&av[0] = *(float4*)&plb[(u * 8 + pgA) * PLPAD + ry];
            *(float4*)&av[4] = *(float4*)&plb[(u * 8 + pgA) * PLPAD + ry + 4];
            *(float4*)&bw[0] = *(float4*)&plb[(u * 8 + pgB) * PLPAD + ry];
            *(float4*)&bw[4] = *(float4*)&plb[(u * 8 + pgB) * PLPAD + ry + 4];
            *(float4*)&tmr[0] = *(float4*)&twb[(u * 4 + 0) * 64 + cx];
            *(float4*)&tsr[0] = *(float4*)&twb[(u * 4 + 1) * 64 + cx];
            *(float4*)&tmi[0] = *(float4*)&twb[(u * 4 + 2) * 64 + cx];
            *(float4*)&tsi[0] = *(float4*)&twb[(u * 4 + 3) * 64 + cx];
            #pragma unroll
            for (int i = 0; i < 8; i++)
                #pragma unroll
                for (int j = 0; j < 4; j++) {
                    accR[i][j] += av[i] * tmr[j] + bw[i] * tsr[j];
                    accI[i][j] += av[i] * tmi[j] + bw[i] * tsi[j];
                }
        }
        __syncthreads();
    }

    int nc[4];
    #pragma unroll
    for (int j = 0; j < 4; j++) nc[j] = d_nc8[zin][tile * 64 + cx + j];
    float* dst = outp + ((size_t)b * HE + he0 + ry) * M2;
    #pragma unroll
    for (int j = 0; j < 4; j++) {
        if (nc[j] >= 0) {
            #pragma unroll
            for (int i = 0; i < 8; i++) {
                dst[(size_t)i * M2 + nc[j]]      = accR[i][j];
                dst[(size_t)i * M2 + 64 + nc[j]] = accI[i][j];
            }
        }
    }
}

// ---------------- stage2+3: qk GEMM + tanh + kv GEMM (round-6 shape) -------
__global__ __launch_bounds__(256) void stage23_k() {
    extern __shared__ float sm[];
    float* Qs  = sm;            // [64][128]
    float* Ks  = sm + 8192;
    float* qkr = sm;            // alias over Qs (after sync)
    float* qki = sm + 4096;

    const int h = blockIdx.x, b = blockIdx.y;
    const int tid = threadIdx.x;

    const size_t off4 = (((size_t)b * HE + h * E_) * M2) / 4;
    for (int i = tid; i < E_ * M2 / 4; i += 256) {
        float4 a0 = ((const float4*)d_QfP[0])[off4 + i];
        float4 a1 = ((const float4*)d_QfP[1])[off4 + i];
        float4 a2 = ((const float4*)d_QfP[2])[off4 + i];
        float4 a3 = ((const float4*)d_QfP[3])[off4 + i];
        ((float4*)Qs)[i] = make_float4(a0.x + a1.x + a2.x + a3.x,
                                       a0.y + a1.y + a2.y + a3.y,
                                       a0.z + a1.z + a2.z + a3.z,
                                       a0.w + a1.w + a2.w + a3.w);
        float4 c0 = ((const float4*)d_KfP[0])[off4 + i];
        float4 c1 = ((const float4*)d_KfP[1])[off4 + i];
        float4 c2 = ((const float4*)d_KfP[2])[off4 + i];
        float4 c3 = ((const float4*)d_KfP[3])[off4 + i];
        ((float4*)Ks)[i] = make_float4(c0.x + c1.x + c2.x + c3.x,
                                       c0.y + c1.y + c2.y + c3.y,
                                       c0.z + c1.z + c2.z + c3.z,
                                       c0.w + c1.w + c2.w + c3.w);
    }
    __syncthreads();

    const int x0 = (tid & 15) * 4;
    {
        int y0 = (tid >> 4) * 4;
        float ar[4][4], ai[4][4];
        #pragma unroll
        for (int yy = 0; yy < 4; yy++)
            #pragma unroll
            for (int xx = 0; xx < 4; xx++) { ar[yy][xx] = 0.f; ai[yy][xx] = 0.f; }
        #pragma unroll 4
        for (int e = 0; e < 64; e++) {
            float4 q4r = *(float4*)&Qs[e * 128 + x0];
            float4 q4i = *(float4*)&Qs[e * 128 + 64 + x0];
            float4 k4r = *(float4*)&Ks[e * 128 + y0];
            float4 k4i = *(float4*)&Ks[e * 128 + 64 + y0];
            float qrv[4] = {q4r.x,q4r.y,q4r.z,q4r.w};
            float qiv[4] = {q4i.x,q4i.y,q4i.z,q4i.w};
            float krv[4] = {k4r.x,k4r.y,k4r.z,k4r.w};
            float kiv[4] = {k4i.x,k4i.y,k4i.z,k4i.w};
            #pragma unroll
            for (int yy = 0; yy < 4; yy++)
                #pragma unroll
                for (int xx = 0; xx < 4; xx++) {
                    ar[yy][xx] += qrv[xx]*krv[yy] - qiv[xx]*kiv[yy];
                    ai[yy][xx] += qrv[xx]*kiv[yy] + qiv[xx]*krv[yy];
                }
        }
        __syncthreads();
        #pragma unroll
        for (int yy = 0; yy < 4; yy++)
            #pragma unroll
            for (int xx = 0; xx < 4; xx++) {
                qkr[(y0 + yy) * 64 + x0 + xx] = tanhf(ar[yy][xx]);
                qki[(y0 + yy) * 64 + x0 + xx] = tanhf(ai[yy][xx]);
            }
    }
    __syncthreads();

    {
        int e0 = (tid >> 4) * 4;
        float cr[4][4], ci[4][4];
        #pragma unroll
        for (int ee = 0; ee < 4; ee++)
            #pragma unroll
            for (int xx = 0; xx < 4; xx++) { cr[ee][xx] = 0.f; ci[ee][xx] = 0.f; }
        #pragma unroll 4
        for (int y = 0; y < 64; y++) {
            float4 q4r = *(float4*)&qkr[y * 64 + x0];
            float4 q4i = *(float4*)&qki[y * 64 + x0];
            float qrv[4] = {q4r.x,q4r.y,q4r.z,q4r.w};
            float qiv[4] = {q4i.x,q4i.y,q4i.z,q4i.w};
            float krv[4], kiv[4];
            #pragma unroll
            for (int ee = 0; ee < 4; ee++) {
                krv[ee] = Ks[(e0 + ee) * 128 + y];
                kiv[ee] = Ks[(e0 + ee) * 128 + 64 + y];
            }
            #pragma unroll
            for (int ee = 0; ee < 4; ee++)
                #pragma unroll
                for (int xx = 0; xx < 4; xx++) {
                    cr[ee][xx] += qrv[xx]*krv[ee] - qiv[xx]*kiv[ee];
                    ci[ee][xx] += qrv[xx]*kiv[ee] + qiv[xx]*krv[ee];
                }
        }
        #pragma unroll
        for (int xx = 0; xx < 4; xx++) {
            size_t base = ((size_t)(h * 64 + x0 + xx) * 2) * 2048 + b * 64 + e0;
            *(float4*)&d_KV[base]        = make_float4(cr[0][xx], cr[1][xx], cr[2][xx], cr[3][xx]);
            *(float4*)&d_KV[base + 2048] = make_float4(ci[0][xx], ci[1][xx], ci[2][xx], ci[3][xx]);
        }
    }
}

// ---------------- stage4: per-(h,mode) pointwise complex GEMM --------------
__global__ __launch_bounds__(128) void xw_k() {
    extern __shared__ float sm[];
    float* kvS = sm;         // [e][c][b]
    float* wS  = sm + 4096;  // [e][c][o]
    const int x = blockIdx.x, h = blockIdx.y;
    const int tid = threadIdx.x;

    {
        const float4* kb = (const float4*)(d_KV + ((size_t)(h * 64 + x) * 2) * 2048);
        #pragma unroll
        for (int r = 0; r < 8; r++) {
            int idx4 = tid + 128 * r;
            float4 v = kb[idx4];
            int e4 = idx4 & 15, bb = (idx4 >> 4) & 31, c = idx4 >> 9;
            #pragma unroll
            for (int j = 0; j < 4; j++)
                kvS[((e4 * 4 + j) * 2 + c) * 32 + bb] = (&v.x)[j];
        }
        const float4* wrb = (const float4*)(d_WTr + (size_t)(h * 64 + x) * 4096);
        const float4* wib = (const float4*)(d_WTi + (size_t)(h * 64 + x) * 4096);
        #pragma unroll
        for (int r = 0; r < 8; r++) {
            int idx4 = tid + 128 * r;
            int e = idx4 >> 4, o4 = idx4 & 15;
            *(float4*)&wS[(e * 2 + 0) * 64 + o4 * 4] = wrb[idx4];
            *(float4*)&wS[(e * 2 + 1) * 64 + o4 * 4] = wib[idx4];
        }
    }
    __syncthreads();

    const int b0 = (tid >> 4) * 4;
    const int o0 = (tid & 15) * 4;
    float cr[4][4], ci[4][4];
    #pragma unroll
    for (int i = 0; i < 4; i++)
        #pragma unroll
        for (int j = 0; j < 4; j++) { cr[i][j] = 0.f; ci[i][j] = 0.f; }

    #pragma unroll 4
    for (int e = 0; e < 64; e++) {
        float4 kr4 = *(float4*)&kvS[(e * 2 + 0) * 32 + b0];
        float4 ki4 = *(float4*)&kvS[(e * 2 + 1) * 32 + b0];
        float4 wr4 = *(float4*)&wS[(e * 2 + 0) * 64 + o0];
        float4 wi4 = *(float4*)&wS[(e * 2 + 1) * 64 + o0];
        float kr[4] = {kr4.x,kr4.y,kr4.z,kr4.w};
        float ki[4] = {ki4.x,ki4.y,ki4.z,ki4.w};
        float wr[4] = {wr4.x,wr4.y,wr4.z,wr4.w};
        float wi[4] = {wi4.x,wi4.y,wi4.z,wi4.w};
        #pragma unroll
        for (int i = 0; i < 4; i++)
            #pragma unroll
            for (int j = 0; j < 4; j++) {
                cr[i][j] += kr[i]*wr[j] - ki[i]*wi[j];
                ci[i][j] += kr[i]*wi[j] + ki[i]*wr[j];
            }
    }
    __syncthreads();

    const float S = 1.0f / 262144.0f;
    #pragma unroll
    for (int i = 0; i < 4; i++) {
        *(float4*)&wS[(0 * 32 + b0 + i) * 64 + o0] =
            make_float4(cr[i][0]*S, cr[i][1]*S, cr[i][2]*S, cr[i][3]*S);
        *(float4*)&wS[(1 * 32 + b0 + i) * 64 + o0] =
            make_float4(ci[i][0]*S, ci[i][1]*S, ci[i][2]*S, ci[i][3]*S);
    }
    __syncthreads();

    int slot = d_pos2slot_q[x];
    #pragma unroll
    for (int r = 0; r < 8; r++) {
        int idx4 = tid + 128 * r;
        int c = idx4 >> 9, bb = (idx4 >> 4) & 31, o4 = idx4 & 15;
        *(float4*)&d_X2T[(size_t)(2 * slot + c) * 16384 + (bb * 8 + h) * 64 + o4 * 4] =
            ((float4*)wS)[idx4];
    }
}

// ---------------- inverse: folded irfft (radix-4) ---------------------------
__global__ __launch_bounds__(256) void inv_fold_k(float* __restrict__ outp) {
    extern __shared__ float sm[];
    float* Ys = sm;
    float* Rr = sm + 8192;
    float* Ri = sm + 12288;
    float* Ir = sm + 16384;
    float* Ii = sm + 18432;
    const int u0 = blockIdx.x * 64;
    const int r0 = blockIdx.y * 64;
    const int tid = threadIdx.x;

    {
        for (int i = tid; i < 2048; i += 256) {
            int p = i >> 4, r4 = (i & 15) * 4;
            float4 v = *(const float4*)&d_X2T[(size_t)p * 16384 + r0 + r4];
            Ys[(r4 + 0) * 128 + p] = v.x;
            Ys[(r4 + 1) * 128 + p] = v.y;
            Ys[(r4 + 2) * 128 + p] = v.z;
            Ys[(r4 + 3) * 128 + p] = v.w;
        }
        for (int i = tid; i < 1024; i += 256) {
            int s = i >> 4, c4 = (i & 15) * 4;
            *(float4*)&Rr[s * 64 + c4] = *(const float4*)&d_TRr[s * 256 + u0 + c4];
            *(float4*)&Ri[s * 64 + c4] = *(const float4*)&d_TRi[s * 256 + u0 + c4];
        }
        for (int i = tid; i < 512; i += 256) {
            int s = i >> 4, c4 = (i & 15) * 4;
            *(float4*)&Ir[s * 64 + c4] = *(const float4*)&d_TIr[s * 256 + u0 + c4];
            *(float4*)&Ii[s * 64 + c4] = *(const float4*)&d_TIi[s * 256 + u0 + c4];
        }
    }
    __syncthreads();

    const int rr = (tid >> 4) * 4;
    const int uu = (tid & 15) * 4;
    float R0[4][4] = {}, R2[4][4] = {}, R1[4][4] = {}, I1[4][4] = {}, R3[4][4] = {}, I3[4][4] = {};

    const int n0 = d_bnd_q[0], n1 = d_bnd_q[1];

#define ACC_R(S, AR) { \
    float4 c4v = *(float4*)&Rr[(S) * 64 + uu]; \
    float4 d4v = *(float4*)&Ri[(S) * 64 + uu]; \
    float cv[4] = {c4v.x,c4v.y,c4v.z,c4v.w}; \
    float dv[4] = {d4v.x,d4v.y,d4v.z,d4v.w}; \
    _Pragma("unroll") \
    for (int r_ = 0; r_ < 4; r_++) { \
        float2 y = *(float2*)&Ys[(rr + r_) * 128 + 2 * (S)]; \
        _Pragma("unroll") \
        for (int u_ = 0; u_ < 4; u_++) AR[r_][u_] += y.x * cv[u_] + y.y * dv[u_]; \
    } }

#define ACC_RI(S, AR, AI) { \
    float4 c4v = *(float4*)&Rr[(S) * 64 + uu]; \
    float4 d4v = *(float4*)&Ri[(S) * 64 + uu]; \
    float4 e4v = *(float4*)&Ir[((S) - 32) * 64 + uu]; \
    float4 f4v = *(float4*)&Ii[((S) - 32) * 64 + uu]; \
    float cv[4] = {c4v.x,c4v.y,c4v.z,c4v.w}; \
    float dv[4] = {d4v.x,d4v.y,d4v.z,d4v.w}; \
    float ev[4] = {e4v.x,e4v.y,e4v.z,e4v.w}; \
    float fv[4] = {f4v.x,f4v.y,f4v.z,f4v.w}; \
    _Pragma("unroll") \
    for (int r_ = 0; r_ < 4; r_++) { \
        float2 y = *(float2*)&Ys[(rr + r_) * 128 + 2 * (S)]; \
        _Pragma("unroll") \
        for (int u_ = 0; u_ < 4; u_++) { \
            AR[r_][u_] += y.x * cv[u_] + y.y * dv[u_]; \
            AI[r_][u_] += y.x * ev[u_] + y.y * fv[u_]; \
        } \
    } }

    for (int s = 0; s < n0; s++)  ACC_R(s, R0);
    for (int s = n0; s < 32; s++) ACC_R(s, R2);
    for (int s = 32; s < n1; s++) ACC_RI(s, R1, I1);
    for (int s = n1; s < 64; s++) ACC_RI(s, R3, I3);

#undef ACC_R
#undef ACC_RI

    #pragma unroll
    for (int r_ = 0; r_ < 4; r_++) {
        float o0[4], o1[4], o2[4], o3[4];
        #pragma unroll
        for (int u_ = 0; u_ < 4; u_++) {
            float rp = R0[r_][u_] + R2[r_][u_];
            float rm = R0[r_][u_] - R2[r_][u_];
            o0[u_] = rp + R1[r_][u_] + R3[r_][u_];
            o1[u_] = rm - I1[r_][u_] + I3[r_][u_];
            o2[u_] = rp - R1[r_][u_] - R3[r_][u_];
            o3[u_] = rm + I1[r_][u_] - I3[r_][u_];
        }
        float* dst = outp + (size_t)(r0 + rr + r_) * L_ + u0 + uu;
        *(float4*)(dst + 0)   = make_float4(o0[0], o0[1], o0[2], o0[3]);
        *(float4*)(dst + 256) = make_float4(o1[0], o1[1], o1[2], o1[3]);
        *(float4*)(dst + 512) = make_float4(o2[0], o2[1], o2[2], o2[3]);
        *(float4*)(dst + 768) = make_float4(o3[0], o3[1], o3[2], o3[3]);
    }
}

// ---------------- launch ---------------------------------------------------
extern "C" void kernel_launch(void* const* d_in, const int* in_sizes, int n_in,
                              void* d_out, int out_size) {
    const float* q   = (const float*)d_in[0];
    const float* k   = (const float*)d_in[1];
    const float* wr  = (const float*)d_in[4];
    const float* wi  = (const float*)d_in[5];
    const int*   iq  = (const int*)d_in[6];
    const int*   ikv = (const int*)d_in[7];
    float* out = (float*)d_out;

    sc_k<<<4, 256>>>();
    meta_k<<<1, 64>>>(iq);
    meta8_k<<<2, 64>>>(iq, ikv);
    tables_k<<<64, 256>>>();
    tables8_k<<<dim3(64, 2), 256>>>();
    wtrans_k<<<dim3(4, 64, 8), 256>>>(wr, wi);
    cudaFuncSetAttribute(dft8m_k, cudaFuncAttributeMaxDynamicSharedMemorySize, 51200);
    dft8m_k<<<dim3(64, B_, 2), 128, 51200>>>(q, k);
    cudaFuncSetAttribute(stage23_k, cudaFuncAttributeMaxDynamicSharedMemorySize, 65536);
    stage23_k<<<dim3(H_, B_), 256, 65536>>>();
    cudaFuncSetAttribute(xw_k, cudaFuncAttributeMaxDynamicSharedMemorySize, 49152);
    xw_k<<<dim3(64, 8), 128, 49152>>>();
    cudaFuncSetAttribute(inv_fold_k, cudaFuncAttributeMaxDynamicSharedMemorySize, 81920);
    inv_fold_k<<<dim3(4, 256), 256, 81920>>>(out);
}

// round 9
// speedup vs baseline: 1.0373x; 1.0119x over previous
#include <cuda_runtime.h>
#include <math.h>

#define B_    32
#define H_    8
#define E_    64
#define M_    64
#define L_    1024
#define DOUT_ 64
#define HE    512
#define M2    128

// ---------------- device scratch ----------------
__device__ float d_QfP[4][B_ * HE * M2];      // q spectrum partials (4-way usplit)
__device__ float d_KfP[4][B_ * HE * M2];
__device__ float d_KV[512 * 2 * 2048];        // kv: [(h*64+x)][c][b*64+e]
__device__ float d_WTr[8 * 64 * 64 * 64];     // wT [h][m][e][o]
__device__ float d_WTi[8 * 64 * 64 * 64];
__device__ float d_X2T[128 * 16384];          // [2*slot+c][(b*8+h)*64+o]
__device__ float2 d_sc[L_];                   // (cos, sin) LUT, fp64-accurate

// radix-8 forward twiddles [z][part(0=re,1=im)][u][128 slots]
__device__ float d_T8m[2][2][128][128];
__device__ float d_T8s[2][2][128][128];
// radix-8 meta
__device__ int d_m8v[2][128];
__device__ int d_pgA8v[2][32];
__device__ int d_pgB8v[2][32];
__device__ int d_p2s8[2][64];        // natural pos -> slot
__device__ int d_Spad8[2];

// inverse tables (q modes, mod-4 scheme)
__device__ float d_TRr[64 * 256], d_TRi[64 * 256], d_TIr[32 * 256], d_TIi[32 * 256];
__device__ int d_slotm_q[64];
__device__ int d_pos2slot_q[64];
__device__ int d_bnd_q[2];

// ---------------- sincos LUT (fp64) ----------------------------------------
__global__ void sc_k() {
    int t = blockIdx.x * 256 + threadIdx.x;   // 0..1023
    const double C = 6.283185307179586476925286766559 / (double)L_;
    double th = C * (double)t;
    d_sc[t] = make_float2((float)cos(th), (float)sin(th));
}

// ---------------- meta for inverse ----------------------------------------
__global__ void meta_k(const int* __restrict__ iq) {
    int j = threadIdx.x;
    __shared__ int mA[64], keys[64];
    mA[j] = iq[j];
    __syncthreads();
    int m = mA[j], c = m & 3;
    int oidx = (c == 0) ? 0 : ((c == 2) ? 1 : ((c == 1) ? 2 : 3));
    keys[j] = oidx * 64 + j;
    __syncthreads();
    int key = keys[j], slot = 0;
    for (int t = 0; t < 64; t++) slot += (keys[t] < key);
    d_slotm_q[slot] = m;
    d_pos2slot_q[j] = slot;
    __syncthreads();
    if (j == 0) {
        int c0 = 0, c1 = 0, c2 = 0;
        for (int t = 0; t < 64; t++) {
            int cc = mA[t] & 3;
            c0 += (cc == 0); c1 += (cc == 1); c2 += (cc == 2);
        }
        d_bnd_q[0] = c0;
        d_bnd_q[1] = c0 + c2 + c1;
    }
}

// ---------------- meta for radix-8 forward ---------------------------------
__global__ void meta8_k(const int* __restrict__ iq, const int* __restrict__ ikv) {
    int z = blockIdx.x, j = threadIdx.x;
    __shared__ int mS[64];
    const int* ix = z ? ikv : iq;
    mS[j] = ix[j];
    __syncthreads();
    if (j == 0) {
        int cS[64], cnt[5] = {0,0,0,0,0};
        for (int t = 0; t < 64; t++) {
            int c = mS[t] & 7;
            int cp = (c <= 4) ? c : 8 - c;
            cS[t] = cp; cnt[cp]++;
        }
        int pb[5], pe[5], acc = 0;
        for (int c = 0; c < 5; c++) { pb[c] = acc; acc += (cnt[c] + 3) & ~3; pe[c] = acc; }
        d_Spad8[z] = acc;
        int posA[128];
        for (int s = 0; s < 128; s++) { d_m8v[z][s] = -1; posA[s] = -1; }
        int fill[5] = {0,0,0,0,0};
        for (int t = 0; t < 64; t++) {
            int s = pb[cS[t]] + fill[cS[t]]++;
            d_m8v[z][s] = mS[t];
            posA[s] = t;
        }
        const int pAt[5] = {0, 2, 4, 6, 1};
        const int pBt[5] = {0, 3, 5, 7, 1};
        for (int g = 0; g < 32; g++) {
            int s0 = g * 4, A = 0, Bp = 0;
            for (int c = 0; c < 5; c++)
                if (cnt[c] > 0 && s0 >= pb[c] && s0 < pe[c]) { A = pAt[c]; Bp = pBt[c]; }
            d_pgA8v[z][g] = A;
            d_pgB8v[z][g] = Bp;
        }
        for (int s = 0; s < 128; s++)
            if (posA[s] >= 0) d_p2s8[z][posA[s]] = s;
    }
}

// ---------------- radix-8 forward tables (LUT gather) ----------------------
__global__ void tables8_k() {
    int z = blockIdx.y;
    int idx = blockIdx.x * 256 + threadIdx.x;   // 0..16383
    int u = idx >> 7, s = idx & 127;
    int m = d_m8v[z][s];
    float tmr = 0.f, tsr = 0.f, tmi = 0.f, tsi = 0.f;
    if (m >= 0) {
        float2 cssn = d_sc[(m * u) & (L_ - 1)];
        int c = m & 7;
        float sg = (c <= 4) ? 1.f : -1.f;
        bool noB = (c == 0) || (c == 4);
        tmr = cssn.x;
        tsr = noB ? 0.f : (sg * cssn.y);
        tmi = -cssn.y;
        tsi = noB ? 0.f : (sg * cssn.x);
    }
    d_T8m[z][0][u][s] = tmr;
    d_T8s[z][0][u][s] = tsr;
    d_T8m[z][1][u][s] = tmi;
    d_T8s[z][1][u][s] = tsi;
}

// ---------------- inverse tables (LUT gather, t-contiguous) -----------------
__global__ void tables_k() {
    int j = blockIdx.x;     // slot 0..63
    int t = threadIdx.x;    // 0..255
    int m = d_slotm_q[j];
    float2 cssn = d_sc[(m * t) & (L_ - 1)];
    float g = ((m == 0) || (2 * m == L_)) ? (1.0f / L_) : (2.0f / L_);
    d_TRr[j * 256 + t] =  g * cssn.x;
    d_TRi[j * 256 + t] = -g * cssn.y;
    if (j >= 32) {
        d_TIr[(j - 32) * 256 + t] = g * cssn.y;
        d_TIi[(j - 32) * 256 + t] = g * cssn.x;
    }
}

// ---------------- w transpose ----------------------------------------------
__global__ __launch_bounds__(256) void wtrans_k(const float* __restrict__ wr_g,
                                                const float* __restrict__ wi_g) {
    __shared__ float tile[32][33];
    const int ot = (blockIdx.x & 1) * 32;
    const int mt = (blockIdx.x >> 1) * 32;
    const int e  = blockIdx.y;
    const int h  = blockIdx.z;
    const int r  = threadIdx.x >> 3;
    const int c4 = (threadIdx.x & 7) * 4;

    for (int z = 0; z < 2; z++) {
        const float* src = z ? wi_g : wr_g;
        float* dst = z ? d_WTi : d_WTr;
        float4 v = *(const float4*)&src[((size_t)(h * 64 + e) * 64 + ot + r) * 64 + mt + c4];
        tile[r][c4 + 0] = v.x; tile[r][c4 + 1] = v.y;
        tile[r][c4 + 2] = v.z; tile[r][c4 + 3] = v.w;
        __syncthreads();
        float4 o;
        o.x = tile[c4 + 0][r]; o.y = tile[c4 + 1][r];
        o.z = tile[c4 + 2][r]; o.w = tile[c4 + 3][r];
        *(float4*)&dst[((size_t)(h * 64 + mt + r) * 64 + e) * 64 + ot + c4] = o;
        __syncthreads();
    }
}

// ---------------- forward: merged radix-8 folded partial DFT ---------------
#define PLPAD 68
#define PLBUF (8 * 8 * PLPAD)
__global__ __launch_bounds__(128, 4) void dft8m_k(const float* __restrict__ qg,
                                                  const float* __restrict__ kg) {
    const int bx   = blockIdx.x;
    const int tile = bx & 1;
    const int us   = (bx >> 1) & 3;
    const int heT  = bx >> 3;
    const int b    = blockIdx.y;
    const int zin  = blockIdx.z;
    if (tile * 64 >= d_Spad8[zin]) return;

    extern __shared__ float sm[];
    float* PL = sm;                  // [2][8u][8pl][68]
    float* TW = sm + 2 * PLBUF;      // [2][8u][4][64]

    const float* __restrict__ x = zin ? kg : qg;
    float* outp = zin ? d_KfP[us] : d_QfP[us];
    const int he0 = heT * 64;
    const int tid = threadIdx.x;
    const int g   = tid & 15;
    const int cx  = g * 4;
    const int ry  = (tid >> 4) * 8;
    const int pgA = d_pgA8v[zin][tile * 16 + g];
    const int pgB = d_pgB8v[zin][tile * 16 + g];
    const float* xb = x + (size_t)b * (L_ * HE) + he0;

    float accR[8][4], accI[8][4];
    #pragma unroll
    for (int i = 0; i < 8; i++)
        #pragma unroll
        for (int j = 0; j < 4; j++) { accR[i][j] = 0.f; accI[i][j] = 0.f; }

    auto load = [&](int ks, int buf) {
        const int u0 = us * 32 + ks * 8;
        float* plb = PL + buf * PLBUF;
        {
            const int ul = tid >> 4;
            const int c4 = (tid & 15) * 4;
            const float* p = xb + (size_t)(u0 + ul) * HE + c4;
            float4 xs[8];
            #pragma unroll
            for (int pp = 0; pp < 8; pp++)
                xs[pp] = *(const float4*)(p + (size_t)pp * 128 * HE);
            float4 pl8[8];
            const float KK = 0.70710678118654752440f;
            #pragma unroll
            for (int q = 0; q < 4; q++) {
                float x0 = (&xs[0].x)[q], x1 = (&xs[1].x)[q], x2 = (&xs[2].x)[q], x3 = (&xs[3].x)[q];
                float x4 = (&xs[4].x)[q], x5 = (&xs[5].x)[q], x6 = (&xs[6].x)[q], x7 = (&xs[7].x)[q];
                float e0 = x0 + x4, e1 = x1 + x5, e2 = x2 + x6, e3 = x3 + x7;
                float o0 = x0 - x4, o1 = x1 - x5, o2 = x2 - x6, o3 = x3 - x7;
                float g0 = e0 + e2, g1 = e1 + e3;
                float t1 = o1 - o3, t2 = o1 + o3;
                float kt1 = KK * t1, kt2 = KK * t2;
                (&pl8[0].x)[q] = g0 + g1;
                (&pl8[1].x)[q] = g0 - g1;
                (&pl8[2].x)[q] = o0 + kt1;
                (&pl8[3].x)[q] = -kt2 - o2;
                (&pl8[4].x)[q] = e0 - e2;
                (&pl8[5].x)[q] = e3 - e1;
                (&pl8[6].x)[q] = o0 - kt1;
                (&pl8[7].x)[q] = o2 - kt2;
            }
            #pragma unroll
            for (int pl = 0; pl < 8; pl++)
                *(float4*)&plb[(ul * 8 + pl) * PLPAD + c4] = pl8[pl];
        }
        float* twb = TW + buf * 2048;
        #pragma unroll
        for (int r = 0; r < 4; r++) {
            int f = tid + 128 * r;
            int uu  = f >> 6;
            int wh  = (f >> 4) & 3;
            int c4t = (f & 15) * 4;
            const float* srcT;
            if (wh == 0)      srcT = &d_T8m[zin][0][u0 + uu][tile * 64];
            else if (wh == 1) srcT = &d_T8s[zin][0][u0 + uu][tile * 64];
            else if (wh == 2) srcT = &d_T8m[zin][1][u0 + uu][tile * 64];
            else              srcT = &d_T8s[zin][1][u0 + uu][tile * 64];
            *(float4*)&twb[(uu * 4 + wh) * 64 + c4t] = *(const float4*)(srcT + c4t);
        }
    };

    load(0, 0);
    __syncthreads();
    #pragma unroll 1
    for (int ks = 0; ks < 4; ks++) {
        int buf = ks & 1;
        if (ks + 1 < 4) load(ks + 1, buf ^ 1);
        float* plb = PL + buf * PLBUF;
        float* twb = TW + buf * 2048;
        #pragma unroll
        for (int u = 0; u < 8; u++) {
            float av[8], bw[8], tmr[4], tsr[4], tmi[4], tsi[4];
            *(float4*)&av[0] = *(float4*)&plb[(u * 8 + pgA) * PLPAD + ry];
            *(float4*)&av[4] = *(float4*)&plb[(u * 8 + pgA) * PLPAD + ry + 4];
            *(float4*)&bw[0] = *(float4*)&plb[(u * 8 + pgB) * PLPAD + ry];
            *(float4*)&bw[4] = *(float4*)&plb[(u * 8 + pgB) * PLPAD + ry + 4];
            *(float4*)&tmr[0] = *(float4*)&twb[(u * 4 + 0) * 64 + cx];
            *(float4*)&tsr[0] = *(float4*)&twb[(u * 4 + 1) * 64 + cx];
            *(float4*)&tmi[0] = *(float4*)&twb[(u * 4 + 2) * 64 + cx];
            *(float4*)&tsi[0] = *(float4*)&twb[(u * 4 + 3) * 64 + cx];
            #pragma unroll
            for (int i = 0; i < 8; i++)
                #pragma unroll
                for (int j = 0; j < 4; j++) {
                    accR[i][j] += av[i] * tmr[j] + bw[i] * tsr[j];
                    accI[i][j] += av[i] * tmi[j] + bw[i] * tsi[j];
                }
        }
        __syncthreads();
    }

    // ---- staged epilogue: smem (swizzled) -> coalesced global stores ----
    // OUT[row 0..63][col 0..127]: Re at slot-col sl, Im at 64+sl.
    // swizzle: col' = col ^ ((col>>5)&1) ^ ((row>>2)&2)  (makes the 4 lane
    // groups per STS bank-disjoint)
    float* OUT = sm;   // reuse PL region (needs 8192 floats; PL has 8704)
    #pragma unroll
    for (int i = 0; i < 8; i++) {
        int row = ry + i;
        int rsw = (row >> 2) & 2;
        #pragma unroll
        for (int j = 0; j < 4; j++) {
            int cR = cx + j;
            OUT[row * 128 + (cR ^ ((cR >> 5) & 1) ^ rsw)] = accR[i][j];
            int cI = 64 + cx + j;
            OUT[row * 128 + (cI ^ ((cI >> 5) & 1) ^ rsw)] = accI[i][j];
        }
    }
    __syncthreads();
    {
        int c = tid;                       // natural output column (0..127)
        int sl = d_p2s8[zin][c & 63];      // slot for this natural pos
        if ((sl >> 6) == tile) {
            int srcCol = (c < 64) ? (sl & 63) : (64 + (sl & 63));
            srcCol ^= (srcCol >> 5) & 1;
            float* dstc = outp + ((size_t)b * HE + he0) * M2 + c;
            #pragma unroll 8
            for (int r = 0; r < 64; r++) {
                float v = OUT[r * 128 + (srcCol ^ ((r >> 2) & 2))];
                dstc[(size_t)r * M2] = v;
            }
        }
    }
}

// ---------------- stage2+3: qk GEMM + tanh + kv GEMM -----------------------
__global__ __launch_bounds__(256) void stage23_k() {
    extern __shared__ float sm[];
    float* Qs  = sm;            // [64][128]
    float* Ks  = sm + 8192;
    float* qkr = sm;            // alias over Qs (after sync)
    float* qki = sm + 4096;

    const int h = blockIdx.x, b = blockIdx.y;
    const int tid = threadIdx.x;

    const size_t off4 = (((size_t)b * HE + h * E_) * M2) / 4;
    for (int i = tid; i < E_ * M2 / 4; i += 256) {
        float4 a0 = ((const float4*)d_QfP[0])[off4 + i];
        float4 a1 = ((const float4*)d_QfP[1])[off4 + i];
        float4 a2 = ((const float4*)d_QfP[2])[off4 + i];
        float4 a3 = ((const float4*)d_QfP[3])[off4 + i];
        ((float4*)Qs)[i] = make_float4(a0.x + a1.x + a2.x + a3.x,
                                       a0.y + a1.y + a2.y + a3.y,
                                       a0.z + a1.z + a2.z + a3.z,
                                       a0.w + a1.w + a2.w + a3.w);
        float4 c0 = ((const float4*)d_KfP[0])[off4 + i];
        float4 c1 = ((const float4*)d_KfP[1])[off4 + i];
        float4 c2 = ((const float4*)d_KfP[2])[off4 + i];
        float4 c3 = ((const float4*)d_KfP[3])[off4 + i];
        ((float4*)Ks)[i] = make_float4(c0.x + c1.x + c2.x + c3.x,
                                       c0.y + c1.y + c2.y + c3.y,
                                       c0.z + c1.z + c2.z + c3.z,
                                       c0.w + c1.w + c2.w + c3.w);
    }
    __syncthreads();

    const int x0 = (tid & 15) * 4;
    {
        int y0 = (tid >> 4) * 4;
        float ar[4][4], ai[4][4];
        #pragma unroll
        for (int yy = 0; yy < 4; yy++)
            #pragma unroll
            for (int xx = 0; xx < 4; xx++) { ar[yy][xx] = 0.f; ai[yy][xx] = 0.f; }
        #pragma unroll 4
        for (int e = 0; e < 64; e++) {
            float4 q4r = *(float4*)&Qs[e * 128 + x0];
            float4 q4i = *(float4*)&Qs[e * 128 + 64 + x0];
            float4 k4r = *(float4*)&Ks[e * 128 + y0];
            float4 k4i = *(float4*)&Ks[e * 128 + 64 + y0];
            float qrv[4] = {q4r.x,q4r.y,q4r.z,q4r.w};
            float qiv[4] = {q4i.x,q4i.y,q4i.z,q4i.w};
            float krv[4] = {k4r.x,k4r.y,k4r.z,k4r.w};
            float kiv[4] = {k4i.x,k4i.y,k4i.z,k4i.w};
            #pragma unroll
            for (int yy = 0; yy < 4; yy++)
                #pragma unroll
                for (int xx = 0; xx < 4; xx++) {
                    ar[yy][xx] += qrv[xx]*krv[yy] - qiv[xx]*kiv[yy];
                    ai[yy][xx] += qrv[xx]*kiv[yy] + qiv[xx]*krv[yy];
                }
        }
        __syncthreads();
        #pragma unroll
        for (int yy = 0; yy < 4; yy++)
            #pragma unroll
            for (int xx = 0; xx < 4; xx++) {
                qkr[(y0 + yy) * 64 + x0 + xx] = tanhf(ar[yy][xx]);
                qki[(y0 + yy) * 64 + x0 + xx] = tanhf(ai[yy][xx]);
            }
    }
    __syncthreads();

    {
        int e0 = (tid >> 4) * 4;
        float cr[4][4], ci[4][4];
        #pragma unroll
        for (int ee = 0; ee < 4; ee++)
            #pragma unroll
            for (int xx = 0; xx < 4; xx++) { cr[ee][xx] = 0.f; ci[ee][xx] = 0.f; }
        #pragma unroll 4
        for (int y = 0; y < 64; y++) {
            float4 q4r = *(float4*)&qkr[y * 64 + x0];
            float4 q4i = *(float4*)&qki[y * 64 + x0];
            float qrv[4] = {q4r.x,q4r.y,q4r.z,q4r.w};
            float qiv[4] = {q4i.x,q4i.y,q4i.z,q4i.w};
            float krv[4], kiv[4];
            #pragma unroll
            for (int ee = 0; ee < 4; ee++) {
                krv[ee] = Ks[(e0 + ee) * 128 + y];
                kiv[ee] = Ks[(e0 + ee) * 128 + 64 + y];
            }
            #pragma unroll
            for (int ee = 0; ee < 4; ee++)
                #pragma unroll
                for (int xx = 0; xx < 4; xx++) {
                    cr[ee][xx] += qrv[xx]*krv[ee] - qiv[xx]*kiv[ee];
                    ci[ee][xx] += qrv[xx]*kiv[ee] + qiv[xx]*krv[ee];
                }
        }
        #pragma unroll
        for (int xx = 0; xx < 4; xx++) {
            size_t base = ((size_t)(h * 64 + x0 + xx) * 2) * 2048 + b * 64 + e0;
            *(float4*)&d_KV[base]        = make_float4(cr[0][xx], cr[1][xx], cr[2][xx], cr[3][xx]);
            *(float4*)&d_KV[base + 2048] = make_float4(ci[0][xx], ci[1][xx], ci[2][xx], ci[3][xx]);
        }
    }
}

// ---------------- stage4: per-(h,mode) pointwise complex GEMM --------------
__global__ __launch_bounds__(128) void xw_k() {
    extern __shared__ float sm[];
    float* kvS = sm;         // [e][c][b]
    float* wS  = sm + 4096;  // [e][c][o]
    const int x = blockIdx.x, h = blockIdx.y;
    const int tid = threadIdx.x;

    {
        const float4* kb = (const float4*)(d_KV + ((size_t)(h * 64 + x) * 2) * 2048);
        #pragma unroll
        for (int r = 0; r < 8; r++) {
            int idx4 = tid + 128 * r;
            float4 v = kb[idx4];
            int e4 = idx4 & 15, bb = (idx4 >> 4) & 31, c = idx4 >> 9;
            #pragma unroll
            for (int j = 0; j < 4; j++)
                kvS[((e4 * 4 + j) * 2 + c) * 32 + bb] = (&v.x)[j];
        }
        const float4* wrb = (const float4*)(d_WTr + (size_t)(h * 64 + x) * 4096);
        const float4* wib = (const float4*)(d_WTi + (size_t)(h * 64 + x) * 4096);
        #pragma unroll
        for (int r = 0; r < 8; r++) {
            int idx4 = tid + 128 * r;
            int e = idx4 >> 4, o4 = idx4 & 15;
            *(float4*)&wS[(e * 2 + 0) * 64 + o4 * 4] = wrb[idx4];
            *(float4*)&wS[(e * 2 + 1) * 64 + o4 * 4] = wib[idx4];
        }
    }
    __syncthreads();

    const int b0 = (tid >> 4) * 4;
    const int o0 = (tid & 15) * 4;
    float cr[4][4], ci[4][4];
    #pragma unroll
    for (int i = 0; i < 4; i++)
        #pragma unroll
        for (int j = 0; j < 4; j++) { cr[i][j] = 0.f; ci[i][j] = 0.f; }

    #pragma unroll 4
    for (int e = 0; e < 64; e++) {
        float4 kr4 = *(float4*)&kvS[(e * 2 + 0) * 32 + b0];
        float4 ki4 = *(float4*)&kvS[(e * 2 + 1) * 32 + b0];
        float4 wr4 = *(float4*)&wS[(e * 2 + 0) * 64 + o0];
        float4 wi4 = *(float4*)&wS[(e * 2 + 1) * 64 + o0];
        float kr[4] = {kr4.x,kr4.y,kr4.z,kr4.w};
        float ki[4] = {ki4.x,ki4.y,ki4.z,ki4.w};
        float wr[4] = {wr4.x,wr4.y,wr4.z,wr4.w};
        float wi[4] = {wi4.x,wi4.y,wi4.z,wi4.w};
        #pragma unroll
        for (int i = 0; i < 4; i++)
            #pragma unroll
            for (int j = 0; j < 4; j++) {
                cr[i][j] += kr[i]*wr[j] - ki[i]*wi[j];
                ci[i][j] += kr[i]*wi[j] + ki[i]*wr[j];
            }
    }
    __syncthreads();

    const float S = 1.0f / 262144.0f;
    #pragma unroll
    for (int i = 0; i < 4; i++) {
        *(float4*)&wS[(0 * 32 + b0 + i) * 64 + o0] =
            make_float4(cr[i][0]*S, cr[i][1]*S, cr[i][2]*S, cr[i][3]*S);
        *(float4*)&wS[(1 * 32 + b0 + i) * 64 + o0] =
            make_float4(ci[i][0]*S, ci[i][1]*S, ci[i][2]*S, ci[i][3]*S);
    }
    __syncthreads();

    int slot = d_pos2slot_q[x];
    #pragma unroll
    for (int r = 0; r < 8; r++) {
        int idx4 = tid + 128 * r;
        int c = idx4 >> 9, bb = (idx4 >> 4) & 31, o4 = idx4 & 15;
        *(float4*)&d_X2T[(size_t)(2 * slot + c) * 16384 + (bb * 8 + h) * 64 + o4 * 4] =
            ((float4*)wS)[idx4];
    }
}

// ---------------- inverse: folded irfft (radix-4) ---------------------------
__global__ __launch_bounds__(256) void inv_fold_k(float* __restrict__ outp) {
    extern __shared__ float sm[];
    float* Ys = sm;
    float* Rr = sm + 8192;
    float* Ri = sm + 12288;
    float* Ir = sm + 16384;
    float* Ii = sm + 18432;
    const int u0 = blockIdx.x * 64;
    const int r0 = blockIdx.y * 64;
    const int tid = threadIdx.x;

    {
        for (int i = tid; i < 2048; i += 256) {
            int p = i >> 4, r4 = (i & 15) * 4;
            float4 v = *(const float4*)&d_X2T[(size_t)p * 16384 + r0 + r4];
            Ys[(r4 + 0) * 128 + p] = v.x;
            Ys[(r4 + 1) * 128 + p] = v.y;
            Ys[(r4 + 2) * 128 + p] = v.z;
            Ys[(r4 + 3) * 128 + p] = v.w;
        }
        for (int i = tid; i < 1024; i += 256) {
            int s = i >> 4, c4 = (i & 15) * 4;
            *(float4*)&Rr[s * 64 + c4] = *(const float4*)&d_TRr[s * 256 + u0 + c4];
            *(float4*)&Ri[s * 64 + c4] = *(const float4*)&d_TRi[s * 256 + u0 + c4];
        }
        for (int i = tid; i < 512; i += 256) {
            int s = i >> 4, c4 = (i & 15) * 4;
            *(float4*)&Ir[s * 64 + c4] = *(const float4*)&d_TIr[s * 256 + u0 + c4];
            *(float4*)&Ii[s * 64 + c4] = *(const float4*)&d_TIi[s * 256 + u0 + c4];
        }
    }
    __syncthreads();

    const int rr = (tid >> 4) * 4;
    const int uu = (tid & 15) * 4;
    float R0[4][4] = {}, R2[4][4] = {}, R1[4][4] = {}, I1[4][4] = {}, R3[4][4] = {}, I3[4][4] = {};

    const int n0 = d_bnd_q[0], n1 = d_bnd_q[1];

#define ACC_R(S, AR) { \
    float4 c4v = *(float4*)&Rr[(S) * 64 + uu]; \
    float4 d4v = *(float4*)&Ri[(S) * 64 + uu]; \
    float cv[4] = {c4v.x,c4v.y,c4v.z,c4v.w}; \
    float dv[4] = {d4v.x,d4v.y,d4v.z,d4v.w}; \
    _Pragma("unroll") \
    for (int r_ = 0; r_ < 4; r_++) { \
        float2 y = *(float2*)&Ys[(rr + r_) * 128 + 2 * (S)]; \
        _Pragma("unroll") \
        for (int u_ = 0; u_ < 4; u_++) AR[r_][u_] += y.x * cv[u_] + y.y * dv[u_]; \
    } }

#define ACC_RI(S, AR, AI) { \
    float4 c4v = *(float4*)&Rr[(S) * 64 + uu]; \
    float4 d4v = *(float4*)&Ri[(S) * 64 + uu]; \
    float4 e4v = *(float4*)&Ir[((S) - 32) * 64 + uu]; \
    float4 f4v = *(float4*)&Ii[((S) - 32) * 64 + uu]; \
    float cv[4] = {c4v.x,c4v.y,c4v.z,c4v.w}; \
    float dv[4] = {d4v.x,d4v.y,d4v.z,d4v.w}; \
    float ev[4] = {e4v.x,e4v.y,e4v.z,e4v.w}; \
    float fv[4] = {f4v.x,f4v.y,f4v.z,f4v.w}; \
    _Pragma("unroll") \
    for (int r_ = 0; r_ < 4; r_++) { \
        float2 y = *(float2*)&Ys[(rr + r_) * 128 + 2 * (S)]; \
        _Pragma("unroll") \
        for (int u_ = 0; u_ < 4; u_++) { \
            AR[r_][u_] += y.x * cv[u_] + y.y * dv[u_]; \
            AI[r_][u_] += y.x * ev[u_] + y.y * fv[u_]; \
        } \
    } }

    for (int s = 0; s < n0; s++)  ACC_R(s, R0);
    for (int s = n0; s < 32; s++) ACC_R(s, R2);
    for (int s = 32; s < n1; s++) ACC_RI(s, R1, I1);
    for (int s = n1; s < 64; s++) ACC_RI(s, R3, I3);

#undef ACC_R
#undef ACC_RI

    #pragma unroll
    for (int r_ = 0; r_ < 4; r_++) {
        float o0[4], o1[4], o2[4], o3[4];
        #pragma unroll
        for (int u_ = 0; u_ < 4; u_++) {
            float rp = R0[r_][u_] + R2[r_][u_];
            float rm = R0[r_][u_] - R2[r_][u_];
            o0[u_] = rp + R1[r_][u_] + R3[r_][u_];
            o1[u_] = rm - I1[r_][u_] + I3[r_][u_];
            o2[u_] = rp - R1[r_][u_] - R3[r_][u_];
            o3[u_] = rm + I1[r_][u_] - I3[r_][u_];
        }
        float* dst = outp + (size_t)(r0 + rr + r_) * L_ + u0 + uu;
        *(float4*)(dst + 0)   = make_float4(o0[0], o0[1], o0[2], o0[3]);
        *(float4*)(dst + 256) = make_float4(o1[0], o1[1], o1[2], o1[3]);
        *(float4*)(dst + 512) = make_float4(o2[0], o2[1], o2[2], o2[3]);
        *(float4*)(dst + 768) = make_float4(o3[0], o3[1], o3[2], o3[3]);
    }
}

// ---------------- launch ---------------------------------------------------
extern "C" void kernel_launch(void* const* d_in, const int* in_sizes, int n_in,
                              void* d_out, int out_size) {
    const float* q   = (const float*)d_in[0];
    const float* k   = (const float*)d_in[1];
    const float* wr  = (const float*)d_in[4];
    const float* wi  = (const float*)d_in[5];
    const int*   iq  = (const int*)d_in[6];
    const int*   ikv = (const int*)d_in[7];
    float* out = (float*)d_out;

    sc_k<<<4, 256>>>();
    meta_k<<<1, 64>>>(iq);
    meta8_k<<<2, 64>>>(iq, ikv);
    tables_k<<<64, 256>>>();
    tables8_k<<<dim3(64, 2), 256>>>();
    wtrans_k<<<dim3(4, 64, 8), 256>>>(wr, wi);
    cudaFuncSetAttribute(dft8m_k, cudaFuncAttributeMaxDynamicSharedMemorySize, 51200);
    dft8m_k<<<dim3(64, B_, 2), 128, 51200>>>(q, k);
    cudaFuncSetAttribute(stage23_k, cudaFuncAttributeMaxDynamicSharedMemorySize, 65536);
    stage23_k<<<dim3(H_, B_), 256, 65536>>>();
    cudaFuncSetAttribute(xw_k, cudaFuncAttributeMaxDynamicSharedMemorySize, 49152);
    xw_k<<<dim3(64, 8), 128, 49152>>>();
    cudaFuncSetAttribute(inv_fold_k, cudaFuncAttributeMaxDynamicSharedMemorySize, 81920);
    inv_fold_k<<<dim3(4, 256), 256, 81920>>>(out);
}

// round 10
// speedup vs baseline: 1.0932x; 1.0539x over previous
#include <cuda_runtime.h>
#include <math.h>

#define B_    32
#define H_    8
#define E_    64
#define M_    64
#define L_    1024
#define DOUT_ 64
#define HE    512
#define M2    128

// ---------------- device scratch ----------------
__device__ float d_QfP[4][B_ * HE * M2];      // q spectrum partials (4-way usplit)
__device__ float d_KfP[4][B_ * HE * M2];
__device__ float d_KV[512 * 2 * 2048];        // kv: [(h*64+x)][c][b*64+e]
__device__ float d_WTr[8 * 64 * 64 * 64];     // wT [h][m][e][o]
__device__ float d_WTi[8 * 64 * 64 * 64];
__device__ float d_X2T[128 * 16384];          // [2*slot+c][(b*8+h)*64+o]
__device__ float2 d_sc[L_];                   // (cos, sin) LUT, fp64-accurate

// radix-8 forward twiddles [z][part(0=re,1=im)][u][128 slots]
__device__ float d_T8m[2][2][128][128];
__device__ float d_T8s[2][2][128][128];
// radix-8 forward meta
__device__ int d_m8v[2][128];
__device__ int d_pgA8v[2][32];
__device__ int d_pgB8v[2][32];
__device__ int d_p2s8[2][64];        // natural pos -> slot
__device__ int d_Spad8[2];

// radix-8 inverse tables [slot][u] (u<128)
__device__ float d_IAr[64 * 128], d_IAi[64 * 128];
__device__ float d_IBr[64 * 128], d_IBi[64 * 128];
// inverse meta (q modes, mod-8 class-sorted: order 0,4,1,2,3 by cp)
__device__ int d_slotm_q[64];
__device__ int d_pos2slot_q[64];
__device__ int d_bnd_q[4];           // n0, n4, n1, n2

// ---------------- sincos LUT (fp64) ----------------------------------------
__global__ void sc_k() {
    int t = blockIdx.x * 256 + threadIdx.x;   // 0..1023
    const double C = 6.283185307179586476925286766559 / (double)L_;
    double th = C * (double)t;
    d_sc[t] = make_float2((float)cos(th), (float)sin(th));
}

// ---------------- meta for inverse (mod-8 class sort) ----------------------
__global__ void meta_k(const int* __restrict__ iq) {
    int j = threadIdx.x;
    __shared__ int mA[64], keys[64];
    mA[j] = iq[j];
    __syncthreads();
    int m = mA[j], c = m & 7;
    int cp = (c <= 4) ? c : 8 - c;
    int rank = (cp == 0) ? 0 : (cp == 4) ? 1 : (cp == 1) ? 2 : (cp == 2) ? 3 : 4;
    keys[j] = rank * 64 + j;
    __syncthreads();
    int key = keys[j], slot = 0;
    for (int t = 0; t < 64; t++) slot += (keys[t] < key);
    d_slotm_q[slot] = m;
    d_pos2slot_q[j] = slot;
    __syncthreads();
    if (j == 0) {
        int cnt[5] = {0, 0, 0, 0, 0};
        for (int t = 0; t < 64; t++) {
            int cc = mA[t] & 7;
            int cpp = (cc <= 4) ? cc : 8 - cc;
            int rr = (cpp == 0) ? 0 : (cpp == 4) ? 1 : (cpp == 1) ? 2 : (cpp == 2) ? 3 : 4;
            cnt[rr]++;
        }
        d_bnd_q[0] = cnt[0];
        d_bnd_q[1] = cnt[0] + cnt[1];
        d_bnd_q[2] = cnt[0] + cnt[1] + cnt[2];
        d_bnd_q[3] = cnt[0] + cnt[1] + cnt[2] + cnt[3];
    }
}

// ---------------- meta for radix-8 forward ---------------------------------
__global__ void meta8_k(const int* __restrict__ iq, const int* __restrict__ ikv) {
    int z = blockIdx.x, j = threadIdx.x;
    __shared__ int mS[64];
    const int* ix = z ? ikv : iq;
    mS[j] = ix[j];
    __syncthreads();
    if (j == 0) {
        int cS[64], cnt[5] = {0,0,0,0,0};
        for (int t = 0; t < 64; t++) {
            int c = mS[t] & 7;
            int cp = (c <= 4) ? c : 8 - c;
            cS[t] = cp; cnt[cp]++;
        }
        int pb[5], pe[5], acc = 0;
        for (int c = 0; c < 5; c++) { pb[c] = acc; acc += (cnt[c] + 3) & ~3; pe[c] = acc; }
        d_Spad8[z] = acc;
        int posA[128];
        for (int s = 0; s < 128; s++) { d_m8v[z][s] = -1; posA[s] = -1; }
        int fill[5] = {0,0,0,0,0};
        for (int t = 0; t < 64; t++) {
            int s = pb[cS[t]] + fill[cS[t]]++;
            d_m8v[z][s] = mS[t];
            posA[s] = t;
        }
        const int pAt[5] = {0, 2, 4, 6, 1};
        const int pBt[5] = {0, 3, 5, 7, 1};
        for (int g = 0; g < 32; g++) {
            int s0 = g * 4, A = 0, Bp = 0;
            for (int c = 0; c < 5; c++)
                if (cnt[c] > 0 && s0 >= pb[c] && s0 < pe[c]) { A = pAt[c]; Bp = pBt[c]; }
            d_pgA8v[z][g] = A;
            d_pgB8v[z][g] = Bp;
        }
        for (int s = 0; s < 128; s++)
            if (posA[s] >= 0) d_p2s8[z][posA[s]] = s;
    }
}

// ---------------- radix-8 forward tables (LUT gather) ----------------------
__global__ void tables8_k() {
    int z = blockIdx.y;
    int idx = blockIdx.x * 256 + threadIdx.x;   // 0..16383
    int u = idx >> 7, s = idx & 127;
    int m = d_m8v[z][s];
    float tmr = 0.f, tsr = 0.f, tmi = 0.f, tsi = 0.f;
    if (m >= 0) {
        float2 cssn = d_sc[(m * u) & (L_ - 1)];
        int c = m & 7;
        float sg = (c <= 4) ? 1.f : -1.f;
        bool noB = (c == 0) || (c == 4);
        tmr = cssn.x;
        tsr = noB ? 0.f : (sg * cssn.y);
        tmi = -cssn.y;
        tsi = noB ? 0.f : (sg * cssn.x);
    }
    d_T8m[z][0][u][s] = tmr;
    d_T8s[z][0][u][s] = tsr;
    d_T8m[z][1][u][s] = tmi;
    d_T8s[z][1][u][s] = tsi;
}

// ---------------- inverse radix-8 tables (LUT gather) -----------------------
// A: multiply (Yr, Yi) for cos-partial; B: sin-partial, conjugate-sign folded.
__global__ void tables_k() {
    int j = blockIdx.x;     // slot 0..63
    int u = threadIdx.x;    // 0..127
    int m = d_slotm_q[j];
    float2 cs = d_sc[(m * u) & (L_ - 1)];
    float g = ((m == 0) || (2 * m == L_)) ? (1.0f / L_) : (2.0f / L_);
    int c = m & 7;
    float sg = (c < 4) ? 1.f : -1.f;
    bool noB = (c == 0) || (c == 4);
    d_IAr[j * 128 + u] =  g * cs.x;
    d_IAi[j * 128 + u] = -g * cs.y;
    d_IBr[j * 128 + u] = noB ? 0.f : (sg * g * cs.y);
    d_IBi[j * 128 + u] = noB ? 0.f : (sg * g * cs.x);
}

// ---------------- w transpose ----------------------------------------------
__global__ __launch_bounds__(256) void wtrans_k(const float* __restrict__ wr_g,
                                                const float* __restrict__ wi_g) {
    __shared__ float tile[32][33];
    const int ot = (blockIdx.x & 1) * 32;
    const int mt = (blockIdx.x >> 1) * 32;
    const int e  = blockIdx.y;
    const int h  = blockIdx.z;
    const int r  = threadIdx.x >> 3;
    const int c4 = (threadIdx.x & 7) * 4;

    for (int z = 0; z < 2; z++) {
        const float* src = z ? wi_g : wr_g;
        float* dst = z ? d_WTi : d_WTr;
        float4 v = *(const float4*)&src[((size_t)(h * 64 + e) * 64 + ot + r) * 64 + mt + c4];
        tile[r][c4 + 0] = v.x; tile[r][c4 + 1] = v.y;
        tile[r][c4 + 2] = v.z; tile[r][c4 + 3] = v.w;
        __syncthreads();
        float4 o;
        o.x = tile[c4 + 0][r]; o.y = tile[c4 + 1][r];
        o.z = tile[c4 + 2][r]; o.w = tile[c4 + 3][r];
        *(float4*)&dst[((size_t)(h * 64 + mt + r) * 64 + e) * 64 + ot + c4] = o;
        __syncthreads();
    }
}

// ---------------- forward: merged radix-8 folded partial DFT ---------------
#define PLPAD 68
#define PLBUF (8 * 8 * PLPAD)
__global__ __launch_bounds__(128, 4) void dft8m_k(const float* __restrict__ qg,
                                                  const float* __restrict__ kg) {
    const int bx   = blockIdx.x;
    const int tile = bx & 1;
    const int us   = (bx >> 1) & 3;
    const int heT  = bx >> 3;
    const int b    = blockIdx.y;
    const int zin  = blockIdx.z;
    if (tile * 64 >= d_Spad8[zin]) return;

    extern __shared__ float sm[];
    float* PL = sm;                  // [2][8u][8pl][68]
    float* TW = sm + 2 * PLBUF;      // [2][8u][4][64]

    const float* __restrict__ x = zin ? kg : qg;
    float* outp = zin ? d_KfP[us] : d_QfP[us];
    const int he0 = heT * 64;
    const int tid = threadIdx.x;
    const int g   = tid & 15;
    const int cx  = g * 4;
    const int ry  = (tid >> 4) * 8;
    const int pgA = d_pgA8v[zin][tile * 16 + g];
    const int pgB = d_pgB8v[zin][tile * 16 + g];
    const float* xb = x + (size_t)b * (L_ * HE) + he0;

    float accR[8][4], accI[8][4];
    #pragma unroll
    for (int i = 0; i < 8; i++)
        #pragma unroll
        for (int j = 0; j < 4; j++) { accR[i][j] = 0.f; accI[i][j] = 0.f; }

    auto load = [&](int ks, int buf) {
        const int u0 = us * 32 + ks * 8;
        float* plb = PL + buf * PLBUF;
        {
            const int ul = tid >> 4;
            const int c4 = (tid & 15) * 4;
            const float* p = xb + (size_t)(u0 + ul) * HE + c4;
            float4 xs[8];
            #pragma unroll
            for (int pp = 0; pp < 8; pp++)
                xs[pp] = *(const float4*)(p + (size_t)pp * 128 * HE);
            float4 pl8[8];
            const float KK = 0.70710678118654752440f;
            #pragma unroll
            for (int q = 0; q < 4; q++) {
                float x0 = (&xs[0].x)[q], x1 = (&xs[1].x)[q], x2 = (&xs[2].x)[q], x3 = (&xs[3].x)[q];
                float x4 = (&xs[4].x)[q], x5 = (&xs[5].x)[q], x6 = (&xs[6].x)[q], x7 = (&xs[7].x)[q];
                float e0 = x0 + x4, e1 = x1 + x5, e2 = x2 + x6, e3 = x3 + x7;
                float o0 = x0 - x4, o1 = x1 - x5, o2 = x2 - x6, o3 = x3 - x7;
                float g0 = e0 + e2, g1 = e1 + e3;
                float t1 = o1 - o3, t2 = o1 + o3;
                float kt1 = KK * t1, kt2 = KK * t2;
                (&pl8[0].x)[q] = g0 + g1;
                (&pl8[1].x)[q] = g0 - g1;
                (&pl8[2].x)[q] = o0 + kt1;
                (&pl8[3].x)[q] = -kt2 - o2;
                (&pl8[4].x)[q] = e0 - e2;
                (&pl8[5].x)[q] = e3 - e1;
                (&pl8[6].x)[q] = o0 - kt1;
                (&pl8[7].x)[q] = o2 - kt2;
            }
            #pragma unroll
            for (int pl = 0; pl < 8; pl++)
                *(float4*)&plb[(ul * 8 + pl) * PLPAD + c4] = pl8[pl];
        }
        float* twb = TW + buf * 2048;
        #pragma unroll
        for (int r = 0; r < 4; r++) {
            int f = tid + 128 * r;
            int uu  = f >> 6;
            int wh  = (f >> 4) & 3;
            int c4t = (f & 15) * 4;
            const float* srcT;
            if (wh == 0)      srcT = &d_T8m[zin][0][u0 + uu][tile * 64];
            else if (wh == 1) srcT = &d_T8s[zin][0][u0 + uu][tile * 64];
            else if (wh == 2) srcT = &d_T8m[zin][1][u0 + uu][tile * 64];
            else              srcT = &d_T8s[zin][1][u0 + uu][tile * 64];
            *(float4*)&twb[(uu * 4 + wh) * 64 + c4t] = *(const float4*)(srcT + c4t);
        }
    };

    load(0, 0);
    __syncthreads();
    #pragma unroll 1
    for (int ks = 0; ks < 4; ks++) {
        int buf = ks & 1;
        if (ks + 1 < 4) load(ks + 1, buf ^ 1);
        float* plb = PL + buf * PLBUF;
        float* twb = TW + buf * 2048;
        #pragma unroll
        for (int u = 0; u < 8; u++) {
            float av[8], bw[8], tmr[4], tsr[4], tmi[4], tsi[4];
            *(float4*)&av[0] = *(float4*)&plb[(u * 8 + pgA) * PLPAD + ry];
            *(float4*)&av[4] = *(float4*)&plb[(u * 8 + pgA) * PLPAD + ry + 4];
            *(float4*)&bw[0] = *(float4*)&plb[(u * 8 + pgB) * PLPAD + ry];
            *(float4*)&bw[4] = *(float4*)&plb[(u * 8 + pgB) * PLPAD + ry + 4];
            *(float4*)&tmr[0] = *(float4*)&twb[(u * 4 + 0) * 64 + cx];
            *(float4*)&tsr[0] = *(float4*)&twb[(u * 4 + 1) * 64 + cx];
            *(float4*)&tmi[0] = *(float4*)&twb[(u * 4 + 2) * 64 + cx];
            *(float4*)&tsi[0] = *(float4*)&twb[(u * 4 + 3) * 64 + cx];
            #pragma unroll
            for (int i = 0; i < 8; i++)
                #pragma unroll
                for (int j = 0; j < 4; j++) {
                    accR[i][j] += av[i] * tmr[j] + bw[i] * tsr[j];
                    accI[i][j] += av[i] * tmi[j] + bw[i] * tsi[j];
                }
        }
        __syncthreads();
    }

    // staged epilogue: swizzled smem -> coalesced global stores
    float* OUT = sm;
    #pragma unroll
    for (int i = 0; i < 8; i++) {
        int row = ry + i;
        int rsw = (row >> 2) & 2;
        #pragma unroll
        for (int j = 0; j < 4; j++) {
            int cR = cx + j;
            OUT[row * 128 + (cR ^ ((cR >> 5) & 1) ^ rsw)] = accR[i][j];
            int cI = 64 + cx + j;
            OUT[row * 128 + (cI ^ ((cI >> 5) & 1) ^ rsw)] = accI[i][j];
        }
    }
    __syncthreads();
    {
        int c = tid;
        int sl = d_p2s8[zin][c & 63];
        if ((sl >> 6) == tile) {
            int srcCol = (c < 64) ? (sl & 63) : (64 + (sl & 63));
            srcCol ^= (srcCol >> 5) & 1;
            float* dstc = outp + ((size_t)b * HE + he0) * M2 + c;
            #pragma unroll 8
            for (int r = 0; r < 64; r++) {
                float v = OUT[r * 128 + (srcCol ^ ((r >> 2) & 2))];
                dstc[(size_t)r * M2] = v;
            }
        }
    }
}

// ---------------- stage2+3: qk GEMM + tanh + kv GEMM -----------------------
__global__ __launch_bounds__(256) void stage23_k() {
    extern __shared__ float sm[];
    float* Qs  = sm;            // [64][128]
    float* Ks  = sm + 8192;
    float* qkr = sm;            // alias over Qs (after sync)
    float* qki = sm + 4096;

    const int h = blockIdx.x, b = blockIdx.y;
    const int tid = threadIdx.x;

    const size_t off4 = (((size_t)b * HE + h * E_) * M2) / 4;
    for (int i = tid; i < E_ * M2 / 4; i += 256) {
        float4 a0 = ((const float4*)d_QfP[0])[off4 + i];
        float4 a1 = ((const float4*)d_QfP[1])[off4 + i];
        float4 a2 = ((const float4*)d_QfP[2])[off4 + i];
        float4 a3 = ((const float4*)d_QfP[3])[off4 + i];
        ((float4*)Qs)[i] = make_float4(a0.x + a1.x + a2.x + a3.x,
                                       a0.y + a1.y + a2.y + a3.y,
                                       a0.z + a1.z + a2.z + a3.z,
                                       a0.w + a1.w + a2.w + a3.w);
        float4 c0 = ((const float4*)d_KfP[0])[off4 + i];
        float4 c1 = ((const float4*)d_KfP[1])[off4 + i];
        float4 c2 = ((const float4*)d_KfP[2])[off4 + i];
        float4 c3 = ((const float4*)d_KfP[3])[off4 + i];
        ((float4*)Ks)[i] = make_float4(c0.x + c1.x + c2.x + c3.x,
                                       c0.y + c1.y + c2.y + c3.y,
                                       c0.z + c1.z + c2.z + c3.z,
                                       c0.w + c1.w + c2.w + c3.w);
    }
    __syncthreads();

    const int x0 = (tid & 15) * 4;
    {
        int y0 = (tid >> 4) * 4;
        float ar[4][4], ai[4][4];
        #pragma unroll
        for (int yy = 0; yy < 4; yy++)
            #pragma unroll
            for (int xx = 0; xx < 4; xx++) { ar[yy][xx] = 0.f; ai[yy][xx] = 0.f; }
        #pragma unroll 4
        for (int e = 0; e < 64; e++) {
            float4 q4r = *(float4*)&Qs[e * 128 + x0];
            float4 q4i = *(float4*)&Qs[e * 128 + 64 + x0];
            float4 k4r = *(float4*)&Ks[e * 128 + y0];
            float4 k4i = *(float4*)&Ks[e * 128 + 64 + y0];
            float qrv[4] = {q4r.x,q4r.y,q4r.z,q4r.w};
            float qiv[4] = {q4i.x,q4i.y,q4i.z,q4i.w};
            float krv[4] = {k4r.x,k4r.y,k4r.z,k4r.w};
            float kiv[4] = {k4i.x,k4i.y,k4i.z,k4i.w};
            #pragma unroll
            for (int yy = 0; yy < 4; yy++)
                #pragma unroll
                for (int xx = 0; xx < 4; xx++) {
                    ar[yy][xx] += qrv[xx]*krv[yy] - qiv[xx]*kiv[yy];
                    ai[yy][xx] += qrv[xx]*kiv[yy] + qiv[xx]*krv[yy];
                }
        }
        __syncthreads();
        #pragma unroll
        for (int yy = 0; yy < 4; yy++)
            #pragma unroll
            for (int xx = 0; xx < 4; xx++) {
                qkr[(y0 + yy) * 64 + x0 + xx] = tanhf(ar[yy][xx]);
                qki[(y0 + yy) * 64 + x0 + xx] = tanhf(ai[yy][xx]);
            }
    }
    __syncthreads();

    {
        int e0 = (tid >> 4) * 4;
        float cr[4][4], ci[4][4];
        #pragma unroll
        for (int ee = 0; ee < 4; ee++)
            #pragma unroll
            for (int xx = 0; xx < 4; xx++) { cr[ee][xx] = 0.f; ci[ee][xx] = 0.f; }
        #pragma unroll 4
        for (int y = 0; y < 64; y++) {
            float4 q4r = *(float4*)&qkr[y * 64 + x0];
            float4 q4i = *(float4*)&qki[y * 64 + x0];
            float qrv[4] = {q4r.x,q4r.y,q4r.z,q4r.w};
            float qiv[4] = {q4i.x,q4i.y,q4i.z,q4i.w};
            float krv[4], kiv[4];
            #pragma unroll
            for (int ee = 0; ee < 4; ee++) {
                krv[ee] = Ks[(e0 + ee) * 128 + y];
                kiv[ee] = Ks[(e0 + ee) * 128 + 64 + y];
            }
            #pragma unroll
            for (int ee = 0; ee < 4; ee++)
                #pragma unroll
                for (int xx = 0; xx < 4; xx++) {
                    cr[ee][xx] += qrv[xx]*krv[ee] - qiv[xx]*kiv[ee];
                    ci[ee][xx] += qrv[xx]*kiv[ee] + qiv[xx]*krv[ee];
                }
        }
        #pragma unroll
        for (int xx = 0; xx < 4; xx++) {
            size_t base = ((size_t)(h * 64 + x0 + xx) * 2) * 2048 + b * 64 + e0;
            *(float4*)&d_KV[base]        = make_float4(cr[0][xx], cr[1][xx], cr[2][xx], cr[3][xx]);
            *(float4*)&d_KV[base + 2048] = make_float4(ci[0][xx], ci[1][xx], ci[2][xx], ci[3][xx]);
        }
    }
}

// ---------------- stage4: per-(h,mode) pointwise complex GEMM --------------
__global__ __launch_bounds__(128) void xw_k() {
    extern __shared__ float sm[];
    float* kvS = sm;         // [e][c][b]
    float* wS  = sm + 4096;  // [e][c][o]
    const int x = blockIdx.x, h = blockIdx.y;
    const int tid = threadIdx.x;

    {
        const float4* kb = (const float4*)(d_KV + ((size_t)(h * 64 + x) * 2) * 2048);
        #pragma unroll
        for (int r = 0; r < 8; r++) {
            int idx4 = tid + 128 * r;
            float4 v = kb[idx4];
            int e4 = idx4 & 15, bb = (idx4 >> 4) & 31, c = idx4 >> 9;
            #pragma unroll
            for (int j = 0; j < 4; j++)
                kvS[((e4 * 4 + j) * 2 + c) * 32 + bb] = (&v.x)[j];
        }
        const float4* wrb = (const float4*)(d_WTr + (size_t)(h * 64 + x) * 4096);
        const float4* wib = (const float4*)(d_WTi + (size_t)(h * 64 + x) * 4096);
        #pragma unroll
        for (int r = 0; r < 8; r++) {
            int idx4 = tid + 128 * r;
            int e = idx4 >> 4, o4 = idx4 & 15;
            *(float4*)&wS[(e * 2 + 0) * 64 + o4 * 4] = wrb[idx4];
            *(float4*)&wS[(e * 2 + 1) * 64 + o4 * 4] = wib[idx4];
        }
    }
    __syncthreads();

    const int b0 = (tid >> 4) * 4;
    const int o0 = (tid & 15) * 4;
    float cr[4][4], ci[4][4];
    #pragma unroll
    for (int i = 0; i < 4; i++)
        #pragma unroll
        for (int j = 0; j < 4; j++) { cr[i][j] = 0.f; ci[i][j] = 0.f; }

    #pragma unroll 4
    for (int e = 0; e < 64; e++) {
        float4 kr4 = *(float4*)&kvS[(e * 2 + 0) * 32 + b0];
        float4 ki4 = *(float4*)&kvS[(e * 2 + 1) * 32 + b0];
        float4 wr4 = *(float4*)&wS[(e * 2 + 0) * 64 + o0];
        float4 wi4 = *(float4*)&wS[(e * 2 + 1) * 64 + o0];
        float kr[4] = {kr4.x,kr4.y,kr4.z,kr4.w};
        float ki[4] = {ki4.x,ki4.y,ki4.z,ki4.w};
        float wr[4] = {wr4.x,wr4.y,wr4.z,wr4.w};
        float wi[4] = {wi4.x,wi4.y,wi4.z,wi4.w};
        #pragma unroll
        for (int i = 0; i < 4; i++)
            #pragma unroll
            for (int j = 0; j < 4; j++) {
                cr[i][j] += kr[i]*wr[j] - ki[i]*wi[j];
                ci[i][j] += kr[i]*wi[j] + ki[i]*wr[j];
            }
    }
    __syncthreads();

    const float S = 1.0f / 262144.0f;
    #pragma unroll
    for (int i = 0; i < 4; i++) {
        *(float4*)&wS[(0 * 32 + b0 + i) * 64 + o0] =
            make_float4(cr[i][0]*S, cr[i][1]*S, cr[i][2]*S, cr[i][3]*S);
        *(float4*)&wS[(1 * 32 + b0 + i) * 64 + o0] =
            make_float4(ci[i][0]*S, ci[i][1]*S, ci[i][2]*S, ci[i][3]*S);
    }
    __syncthreads();

    int slot = d_pos2slot_q[x];
    #pragma unroll
    for (int r = 0; r < 8; r++) {
        int idx4 = tid + 128 * r;
        int c = idx4 >> 9, bb = (idx4 >> 4) & 31, o4 = idx4 & 15;
        *(float4*)&d_X2T[(size_t)(2 * slot + c) * 16384 + (bb * 8 + h) * 64 + o4 * 4] =
            ((float4*)wS)[idx4];
    }
}

// ---------------- inverse: radix-8 folded irfft -----------------------------
// grid (4 u-blocks, 256 row-blocks); block 256 thr = 16 rgrp x 16 ugrp
// each thread: [4 rows][2 u], 8 partial-sum groups, 8-point combine.
__global__ __launch_bounds__(256) void inv8_k(float* __restrict__ outp) {
    extern __shared__ float sm[];
    float* Ys = sm;              // [64 rows][128]
    float* Ar = sm + 8192;       // [64 slots][32 u]
    float* Ai = sm + 10240;
    float* Br = sm + 12288;
    float* Bi = sm + 14336;
    const int u0 = blockIdx.x * 32;
    const int r0 = blockIdx.y * 64;
    const int tid = threadIdx.x;

    for (int i = tid; i < 2048; i += 256) {
        int p = i >> 4, r4 = (i & 15) * 4;
        float4 v = *(const float4*)&d_X2T[(size_t)p * 16384 + r0 + r4];
        Ys[(r4 + 0) * 128 + p] = v.x;
        Ys[(r4 + 1) * 128 + p] = v.y;
        Ys[(r4 + 2) * 128 + p] = v.z;
        Ys[(r4 + 3) * 128 + p] = v.w;
    }
    for (int i = tid; i < 512; i += 256) {
        int s = i >> 3, f = (i & 7) * 4;
        *(float4*)&Ar[s * 32 + f] = *(const float4*)&d_IAr[s * 128 + u0 + f];
        *(float4*)&Ai[s * 32 + f] = *(const float4*)&d_IAi[s * 128 + u0 + f];
        *(float4*)&Br[s * 32 + f] = *(const float4*)&d_IBr[s * 128 + u0 + f];
        *(float4*)&Bi[s * 32 + f] = *(const float4*)&d_IBi[s * 128 + u0 + f];
    }
    __syncthreads();

    const int rr = (tid >> 4) * 4;
    const int uu = (tid & 15) * 2;
    float A0[4][2] = {}, A4[4][2] = {};
    float A1[4][2] = {}, B1[4][2] = {};
    float A2[4][2] = {}, B2[4][2] = {};
    float A3[4][2] = {}, B3[4][2] = {};

    const int n0 = d_bnd_q[0], n4 = d_bnd_q[1], n1 = d_bnd_q[2], n2 = d_bnd_q[3];

#define IACC_A(S, A) { \
    float2 a2 = *(float2*)&Ar[(S) * 32 + uu]; \
    float2 i2 = *(float2*)&Ai[(S) * 32 + uu]; \
    _Pragma("unroll") \
    for (int r_ = 0; r_ < 4; r_++) { \
        float2 y = *(float2*)&Ys[(rr + r_) * 128 + 2 * (S)]; \
        A[r_][0] += y.x * a2.x + y.y * i2.x; \
        A[r_][1] += y.x * a2.y + y.y * i2.y; \
    } }

#define IACC_AB(S, A, Bm) { \
    float2 a2 = *(float2*)&Ar[(S) * 32 + uu]; \
    float2 i2 = *(float2*)&Ai[(S) * 32 + uu]; \
    float2 b2 = *(float2*)&Br[(S) * 32 + uu]; \
    float2 c2 = *(float2*)&Bi[(S) * 32 + uu]; \
    _Pragma("unroll") \
    for (int r_ = 0; r_ < 4; r_++) { \
        float2 y = *(float2*)&Ys[(rr + r_) * 128 + 2 * (S)]; \
        A[r_][0]  += y.x * a2.x + y.y * i2.x; \
        A[r_][1]  += y.x * a2.y + y.y * i2.y; \
        Bm[r_][0] += y.x * b2.x + y.y * c2.x; \
        Bm[r_][1] += y.x * b2.y + y.y * c2.y; \
    } }

    for (int s = 0;  s < n0; s++) IACC_A(s, A0);
    for (int s = n0; s < n4; s++) IACC_A(s, A4);
    for (int s = n4; s < n1; s++) IACC_AB(s, A1, B1);
    for (int s = n1; s < n2; s++) IACC_AB(s, A2, B2);
    for (int s = n2; s < 64; s++) IACC_AB(s, A3, B3);

#undef IACC_A
#undef IACC_AB

    const float K = 0.70710678118654752440f;
    #pragma unroll
    for (int r_ = 0; r_ < 4; r_++) {
        float ov[8][2];
        #pragma unroll
        for (int u_ = 0; u_ < 2; u_++) {
            float a0 = A0[r_][u_], a4 = A4[r_][u_];
            float a1 = A1[r_][u_], b1 = B1[r_][u_];
            float a2 = A2[r_][u_], b2 = B2[r_][u_];
            float a3 = A3[r_][u_], b3 = B3[r_][u_];
            float pA = a0 + a4, mA = a0 - a4;
            float s1p = K * (a1 - b1), s1m = K * (a1 + b1);
            float s3p = K * (a3 + b3), s3m = K * (a3 - b3);
            ov[0][u_] = pA + a1 + a2 + a3;
            ov[1][u_] = mA + s1p - b2 - s3p;
            ov[2][u_] = pA - b1 - a2 + b3;
            ov[3][u_] = mA - s1m + b2 + s3m;
            ov[4][u_] = pA - a1 + a2 - a3;
            ov[5][u_] = mA - s1p - b2 + s3p;
            ov[6][u_] = pA + b1 - a2 - b3;
            ov[7][u_] = mA + s1m + b2 - s3m;
        }
        float* dst = outp + (size_t)(r0 + rr + r_) * L_ + u0 + uu;
        #pragma unroll
        for (int p = 0; p < 8; p++)
            *(float2*)(dst + 128 * p) = make_float2(ov[p][0], ov[p][1]);
    }
}

// ---------------- launch ---------------------------------------------------
extern "C" void kernel_launch(void* const* d_in, const int* in_sizes, int n_in,
                              void* d_out, int out_size) {
    const float* q   = (const float*)d_in[0];
    const float* k   = (const float*)d_in[1];
    const float* wr  = (const float*)d_in[4];
    const float* wi  = (const float*)d_in[5];
    const int*   iq  = (const int*)d_in[6];
    const int*   ikv = (const int*)d_in[7];
    float* out = (float*)d_out;

    sc_k<<<4, 256>>>();
    meta_k<<<1, 64>>>(iq);
    meta8_k<<<2, 64>>>(iq, ikv);
    tables_k<<<64, 128>>>();
    tables8_k<<<dim3(64, 2), 256>>>();
    wtrans_k<<<dim3(4, 64, 8), 256>>>(wr, wi);
    cudaFuncSetAttribute(dft8m_k, cudaFuncAttributeMaxDynamicSharedMemorySize, 51200);
    dft8m_k<<<dim3(64, B_, 2), 128, 51200>>>(q, k);
    cudaFuncSetAttribute(stage23_k, cudaFuncAttributeMaxDynamicSharedMemorySize, 65536);
    stage23_k<<<dim3(H_, B_), 256, 65536>>>();
    cudaFuncSetAttribute(xw_k, cudaFuncAttributeMaxDynamicSharedMemorySize, 49152);
    xw_k<<<dim3(64, 8), 128, 49152>>>();
    cudaFuncSetAttribute(inv8_k, cudaFuncAttributeMaxDynamicSharedMemorySize, 65536);
    inv8_k<<<dim3(4, 256), 256, 65536>>>(out);
}

// round 11
// speedup vs baseline: 1.1414x; 1.0441x over previous
#include <cuda_runtime.h>
#include <math.h>

#define B_    32
#define H_    8
#define E_    64
#define M_    64
#define L_    1024
#define DOUT_ 64
#define HE    512
#define M2    128

// ---------------- device scratch ----------------
__device__ float d_QfP[4][B_ * HE * M2];
__device__ float d_KfP[4][B_ * HE * M2];
__device__ float d_KV[512 * 2 * 2048];
__device__ float d_WTr[8 * 64 * 64 * 64];
__device__ float d_WTi[8 * 64 * 64 * 64];
__device__ float d_X2T[128 * 16384];
__device__ float2 d_sc[L_];

// radix-8 forward twiddles [z][part][u][128 slots]
__device__ float d_T8m[2][2][128][128];
__device__ float d_T8s[2][2][128][128];
__device__ int d_m8v[2][128];
__device__ int d_pgA8v[2][32];
__device__ int d_pgB8v[2][32];
__device__ int d_p2s8[2][64];
__device__ int d_Spad8[2];

// radix-8 inverse tables [slot][u<128]
__device__ float d_IAr[64 * 128], d_IAi[64 * 128];
__device__ float d_IBr[64 * 128], d_IBi[64 * 128];
__device__ int d_slotm_q[64];
__device__ int d_pos2slot_q[64];
__device__ int d_bnd_q[4];

// ---------------- setup1: sc LUT + both metas (one launch) -----------------
__global__ void setup1_k(const int* __restrict__ iq, const int* __restrict__ ikv) {
    __shared__ int mA[64], keys[64], s2p[128];
    const int bx = blockIdx.x, tid = threadIdx.x;
    if (bx < 4) {
        int t = bx * 256 + tid;
        const double C = 6.283185307179586476925286766559 / (double)L_;
        double th = C * (double)t;
        d_sc[t] = make_float2((float)cos(th), (float)sin(th));
        return;
    }
    if (bx == 4) {
        // inverse meta: mod-8 class sort of q modes (rank order cp: 0,4,1,2,3)
        if (tid < 64) mA[tid] = iq[tid];
        __syncthreads();
        if (tid < 64) {
            int m = mA[tid], c = m & 7;
            int cp = (c <= 4) ? c : 8 - c;
            int rank = (cp == 0) ? 0 : (cp == 4) ? 1 : (cp == 1) ? 2 : (cp == 2) ? 3 : 4;
            keys[tid] = rank * 64 + tid;
        }
        __syncthreads();
        if (tid < 64) {
            int key = keys[tid], slot = 0;
            for (int t = 0; t < 64; t++) slot += (keys[t] < key);
            d_slotm_q[slot] = mA[tid];
            d_pos2slot_q[tid] = slot;
        }
        __syncthreads();
        if (tid == 0) {
            int cnt[5] = {0, 0, 0, 0, 0};
            for (int t = 0; t < 64; t++) {
                int cc = mA[t] & 7;
                int cpp = (cc <= 4) ? cc : 8 - cc;
                int rr = (cpp == 0) ? 0 : (cpp == 4) ? 1 : (cpp == 1) ? 2 : (cpp == 2) ? 3 : 4;
                cnt[rr]++;
            }
            d_bnd_q[0] = cnt[0];
            d_bnd_q[1] = cnt[0] + cnt[1];
            d_bnd_q[2] = cnt[0] + cnt[1] + cnt[2];
            d_bnd_q[3] = cnt[0] + cnt[1] + cnt[2] + cnt[3];
        }
        return;
    }
    {
        // forward radix-8 meta, z = bx - 5
        int z = bx - 5;
        const int* ix = z ? ikv : iq;
        if (tid < 64) mA[tid] = ix[tid];
        __syncthreads();
        if (tid == 0) {
            int cS[64], cnt[5] = {0,0,0,0,0};
            for (int t = 0; t < 64; t++) {
                int c = mA[t] & 7;
                int cp = (c <= 4) ? c : 8 - c;
                cS[t] = cp; cnt[cp]++;
            }
            int pb[5], pe[5], acc = 0;
            for (int c = 0; c < 5; c++) { pb[c] = acc; acc += (cnt[c] + 3) & ~3; pe[c] = acc; }
            d_Spad8[z] = acc;
            for (int s = 0; s < 128; s++) { d_m8v[z][s] = -1; s2p[s] = -1; }
            int fill[5] = {0,0,0,0,0};
            for (int t = 0; t < 64; t++) {
                int s = pb[cS[t]] + fill[cS[t]]++;
                d_m8v[z][s] = mA[t];
                s2p[s] = t;
            }
            const int pAt[5] = {0, 2, 4, 6, 1};
            const int pBt[5] = {0, 3, 5, 7, 1};
            for (int g = 0; g < 32; g++) {
                int s0 = g * 4, A = 0, Bp = 0;
                for (int c = 0; c < 5; c++)
                    if (cnt[c] > 0 && s0 >= pb[c] && s0 < pe[c]) { A = pAt[c]; Bp = pBt[c]; }
                d_pgA8v[z][g] = A;
                d_pgB8v[z][g] = Bp;
            }
            for (int s = 0; s < 128; s++)
                if (s2p[s] >= 0) d_p2s8[z][s2p[s]] = s;
        }
    }
}

// ---------------- setup2: all twiddle tables (one launch) -------------------
__global__ void setup2_k() {
    const int bx = blockIdx.x, tid = threadIdx.x;
    if (bx < 32) {
        // inverse radix-8 tables: 64 slots x 128 u
        int idx = bx * 256 + tid;
        int j = idx >> 7, u = idx & 127;
        int m = d_slotm_q[j];
        float2 cs = d_sc[(m * u) & (L_ - 1)];
        float g = ((m == 0) || (2 * m == L_)) ? (1.0f / L_) : (2.0f / L_);
        int c = m & 7;
        float sg = (c < 4) ? 1.f : -1.f;
        bool noB = (c == 0) || (c == 4);
        d_IAr[j * 128 + u] =  g * cs.x;
        d_IAi[j * 128 + u] = -g * cs.y;
        d_IBr[j * 128 + u] = noB ? 0.f : (sg * g * cs.y);
        d_IBi[j * 128 + u] = noB ? 0.f : (sg * g * cs.x);
    } else {
        // forward radix-8 tables: z in {0,1}, 128 u x 128 slots
        int r = bx - 32;
        int z = r >> 6;
        int idx = (r & 63) * 256 + tid;
        int u = idx >> 7, s = idx & 127;
        int m = d_m8v[z][s];
        float tmr = 0.f, tsr = 0.f, tmi = 0.f, tsi = 0.f;
        if (m >= 0) {
            float2 cssn = d_sc[(m * u) & (L_ - 1)];
            int c = m & 7;
            float sg = (c <= 4) ? 1.f : -1.f;
            bool noB = (c == 0) || (c == 4);
            tmr = cssn.x;
            tsr = noB ? 0.f : (sg * cssn.y);
            tmi = -cssn.y;
            tsi = noB ? 0.f : (sg * cssn.x);
        }
        d_T8m[z][0][u][s] = tmr;
        d_T8s[z][0][u][s] = tsr;
        d_T8m[z][1][u][s] = tmi;
        d_T8s[z][1][u][s] = tsi;
    }
}

// ---------------- w transpose ----------------------------------------------
__global__ __launch_bounds__(256) void wtrans_k(const float* __restrict__ wr_g,
                                                const float* __restrict__ wi_g) {
    __shared__ float tile[32][33];
    const int ot = (blockIdx.x & 1) * 32;
    const int mt = (blockIdx.x >> 1) * 32;
    const int e  = blockIdx.y;
    const int h  = blockIdx.z;
    const int r  = threadIdx.x >> 3;
    const int c4 = (threadIdx.x & 7) * 4;

    for (int z = 0; z < 2; z++) {
        const float* src = z ? wi_g : wr_g;
        float* dst = z ? d_WTi : d_WTr;
        float4 v = *(const float4*)&src[((size_t)(h * 64 + e) * 64 + ot + r) * 64 + mt + c4];
        tile[r][c4 + 0] = v.x; tile[r][c4 + 1] = v.y;
        tile[r][c4 + 2] = v.z; tile[r][c4 + 3] = v.w;
        __syncthreads();
        float4 o;
        o.x = tile[c4 + 0][r]; o.y = tile[c4 + 1][r];
        o.z = tile[c4 + 2][r]; o.w = tile[c4 + 3][r];
        *(float4*)&dst[((size_t)(h * 64 + mt + r) * 64 + e) * 64 + ot + c4] = o;
        __syncthreads();
    }
}

// ---------------- forward: merged radix-8 folded partial DFT ---------------
#define PLPAD 68
#define PLBUF (8 * 8 * PLPAD)
__global__ __launch_bounds__(128, 4) void dft8m_k(const float* __restrict__ qg,
                                                  const float* __restrict__ kg) {
    const int bx   = blockIdx.x;
    const int tile = bx & 1;
    const int us   = (bx >> 1) & 3;
    const int heT  = bx >> 3;
    const int b    = blockIdx.y;
    const int zin  = blockIdx.z;
    if (tile * 64 >= d_Spad8[zin]) return;

    extern __shared__ float sm[];
    float* PL = sm;
    float* TW = sm + 2 * PLBUF;

    const float* __restrict__ x = zin ? kg : qg;
    float* outp = zin ? d_KfP[us] : d_QfP[us];
    const int he0 = heT * 64;
    const int tid = threadIdx.x;
    const int g   = tid & 15;
    const int cx  = g * 4;
    const int ry  = (tid >> 4) * 8;
    const int pgA = d_pgA8v[zin][tile * 16 + g];
    const int pgB = d_pgB8v[zin][tile * 16 + g];
    const float* xb = x + (size_t)b * (L_ * HE) + he0;

    float accR[8][4], accI[8][4];
    #pragma unroll
    for (int i = 0; i < 8; i++)
        #pragma unroll
        for (int j = 0; j < 4; j++) { accR[i][j] = 0.f; accI[i][j] = 0.f; }

    auto load = [&](int ks, int buf) {
        const int u0 = us * 32 + ks * 8;
        float* plb = PL + buf * PLBUF;
        {
            const int ul = tid >> 4;
            const int c4 = (tid & 15) * 4;
            const float* p = xb + (size_t)(u0 + ul) * HE + c4;
            float4 xs[8];
            #pragma unroll
            for (int pp = 0; pp < 8; pp++)
                xs[pp] = *(const float4*)(p + (size_t)pp * 128 * HE);
            float4 pl8[8];
            const float KK = 0.70710678118654752440f;
            #pragma unroll
            for (int q = 0; q < 4; q++) {
                float x0 = (&xs[0].x)[q], x1 = (&xs[1].x)[q], x2 = (&xs[2].x)[q], x3 = (&xs[3].x)[q];
                float x4 = (&xs[4].x)[q], x5 = (&xs[5].x)[q], x6 = (&xs[6].x)[q], x7 = (&xs[7].x)[q];
                float e0 = x0 + x4, e1 = x1 + x5, e2 = x2 + x6, e3 = x3 + x7;
                float o0 = x0 - x4, o1 = x1 - x5, o2 = x2 - x6, o3 = x3 - x7;
                float g0 = e0 + e2, g1 = e1 + e3;
                float t1 = o1 - o3, t2 = o1 + o3;
                float kt1 = KK * t1, kt2 = KK * t2;
                (&pl8[0].x)[q] = g0 + g1;
                (&pl8[1].x)[q] = g0 - g1;
                (&pl8[2].x)[q] = o0 + kt1;
                (&pl8[3].x)[q] = -kt2 - o2;
                (&pl8[4].x)[q] = e0 - e2;
                (&pl8[5].x)[q] = e3 - e1;
                (&pl8[6].x)[q] = o0 - kt1;
                (&pl8[7].x)[q] = o2 - kt2;
            }
            #pragma unroll
            for (int pl = 0; pl < 8; pl++)
                *(float4*)&plb[(ul * 8 + pl) * PLPAD + c4] = pl8[pl];
        }
        float* twb = TW + buf * 2048;
        #pragma unroll
        for (int r = 0; r < 4; r++) {
            int f = tid + 128 * r;
            int uu  = f >> 6;
            int wh  = (f >> 4) & 3;
            int c4t = (f & 15) * 4;
            const float* srcT;
            if (wh == 0)      srcT = &d_T8m[zin][0][u0 + uu][tile * 64];
            else if (wh == 1) srcT = &d_T8s[zin][0][u0 + uu][tile * 64];
            else if (wh == 2) srcT = &d_T8m[zin][1][u0 + uu][tile * 64];
            else              srcT = &d_T8s[zin][1][u0 + uu][tile * 64];
            *(float4*)&twb[(uu * 4 + wh) * 64 + c4t] = *(const float4*)(srcT + c4t);
        }
    };

    load(0, 0);
    __syncthreads();
    #pragma unroll 1
    for (int ks = 0; ks < 4; ks++) {
        int buf = ks & 1;
        if (ks + 1 < 4) load(ks + 1, buf ^ 1);
        float* plb = PL + buf * PLBUF;
        float* twb = TW + buf * 2048;
        #pragma unroll
        for (int u = 0; u < 8; u++) {
            float av[8], bw[8], tmr[4], tsr[4], tmi[4], tsi[4];
            *(float4*)&av[0] = *(float4*)&plb[(u * 8 + pgA) * PLPAD + ry];
            *(float4*)&av[4] = *(float4*)&plb[(u * 8 + pgA) * PLPAD + ry + 4];
            *(float4*)&bw[0] = *(float4*)&plb[(u * 8 + pgB) * PLPAD + ry];
            *(float4*)&bw[4] = *(float4*)&plb[(u * 8 + pgB) * PLPAD + ry + 4];
            *(float4*)&tmr[0] = *(float4*)&twb[(u * 4 + 0) * 64 + cx];
            *(float4*)&tsr[0] = *(float4*)&twb[(u * 4 + 1) * 64 + cx];
            *(float4*)&tmi[0] = *(float4*)&twb[(u * 4 + 2) * 64 + cx];
            *(float4*)&tsi[0] = *(float4*)&twb[(u * 4 + 3) * 64 + cx];
            #pragma unroll
            for (int i = 0; i < 8; i++)
                #pragma unroll
                for (int j = 0; j < 4; j++) {
                    accR[i][j] += av[i] * tmr[j] + bw[i] * tsr[j];
                    accI[i][j] += av[i] * tmi[j] + bw[i] * tsi[j];
                }
        }
        __syncthreads();
    }

    // staged epilogue: swizzled smem -> coalesced global stores
    float* OUT = sm;
    #pragma unroll
    for (int i = 0; i < 8; i++) {
        int row = ry + i;
        int rsw = (row >> 2) & 2;
        #pragma unroll
        for (int j = 0; j < 4; j++) {
            int cR = cx + j;
            OUT[row * 128 + (cR ^ ((cR >> 5) & 1) ^ rsw)] = accR[i][j];
            int cI = 64 + cx + j;
            OUT[row * 128 + (cI ^ ((cI >> 5) & 1) ^ rsw)] = accI[i][j];
        }
    }
    __syncthreads();
    {
        int c = tid;
        int sl = d_p2s8[zin][c & 63];
        if ((sl >> 6) == tile) {
            int srcCol = (c < 64) ? (sl & 63) : (64 + (sl & 63));
            srcCol ^= (srcCol >> 5) & 1;
            float* dstc = outp + ((size_t)b * HE + he0) * M2 + c;
            #pragma unroll 8
            for (int r = 0; r < 64; r++) {
                float v = OUT[r * 128 + (srcCol ^ ((r >> 2) & 2))];
                dstc[(size_t)r * M2] = v;
            }
        }
    }
}

// ---------------- stage2+3: qk GEMM + tanh + kv GEMM (512 thr) -------------
__global__ __launch_bounds__(512) void stage23_k() {
    extern __shared__ float sm[];
    float* Qs  = sm;            // [64][128]
    float* Ks  = sm + 8192;
    float* qkr = sm;            // alias over Qs (after sync)
    float* qki = sm + 4096;

    const int h = blockIdx.x, b = blockIdx.y;
    const int tid = threadIdx.x;

    const size_t off4 = (((size_t)b * HE + h * E_) * M2) / 4;
    for (int i = tid; i < E_ * M2 / 4; i += 512) {
        float4 a0 = ((const float4*)d_QfP[0])[off4 + i];
        float4 a1 = ((const float4*)d_QfP[1])[off4 + i];
        float4 a2 = ((const float4*)d_QfP[2])[off4 + i];
        float4 a3 = ((const float4*)d_QfP[3])[off4 + i];
        ((float4*)Qs)[i] = make_float4(a0.x + a1.x + a2.x + a3.x,
                                       a0.y + a1.y + a2.y + a3.y,
                                       a0.z + a1.z + a2.z + a3.z,
                                       a0.w + a1.w + a2.w + a3.w);
        float4 c0 = ((const float4*)d_KfP[0])[off4 + i];
        float4 c1 = ((const float4*)d_KfP[1])[off4 + i];
        float4 c2 = ((const float4*)d_KfP[2])[off4 + i];
        float4 c3 = ((const float4*)d_KfP[3])[off4 + i];
        ((float4*)Ks)[i] = make_float4(c0.x + c1.x + c2.x + c3.x,
                                       c0.y + c1.y + c2.y + c3.y,
                                       c0.z + c1.z + c2.z + c3.z,
                                       c0.w + c1.w + c2.w + c3.w);
    }
    __syncthreads();

    const int x0 = (tid & 15) * 4;
    const int yg = tid >> 4;         // 0..31
    {
        int y0 = yg * 2;
        float ar[2][4], ai[2][4];
        #pragma unroll
        for (int yy = 0; yy < 2; yy++)
            #pragma unroll
            for (int xx = 0; xx < 4; xx++) { ar[yy][xx] = 0.f; ai[yy][xx] = 0.f; }
        #pragma unroll 4
        for (int e = 0; e < 64; e++) {
            float4 q4r = *(float4*)&Qs[e * 128 + x0];
            float4 q4i = *(float4*)&Qs[e * 128 + 64 + x0];
            float2 k2r = *(float2*)&Ks[e * 128 + y0];
            float2 k2i = *(float2*)&Ks[e * 128 + 64 + y0];
            float qrv[4] = {q4r.x,q4r.y,q4r.z,q4r.w};
            float qiv[4] = {q4i.x,q4i.y,q4i.z,q4i.w};
            float krv[2] = {k2r.x,k2r.y};
            float kiv[2] = {k2i.x,k2i.y};
            #pragma unroll
            for (int yy = 0; yy < 2; yy++)
                #pragma unroll
                for (int xx = 0; xx < 4; xx++) {
                    ar[yy][xx] += qrv[xx]*krv[yy] - qiv[xx]*kiv[yy];
                    ai[yy][xx] += qrv[xx]*kiv[yy] + qiv[xx]*krv[yy];
                }
        }
        __syncthreads();   // Qs reads done before aliased qk write
        #pragma unroll
        for (int yy = 0; yy < 2; yy++)
            #pragma unroll
            for (int xx = 0; xx < 4; xx++) {
                qkr[(y0 + yy) * 64 + x0 + xx] = tanhf(ar[yy][xx]);
                qki[(y0 + yy) * 64 + x0 + xx] = tanhf(ai[yy][xx]);
            }
    }
    __syncthreads();

    {
        int e0 = yg * 2;
        float cr[2][4], ci[2][4];
        #pragma unroll
        for (int ee = 0; ee < 2; ee++)
            #pragma unroll
            for (int xx = 0; xx < 4; xx++) { cr[ee][xx] = 0.f; ci[ee][xx] = 0.f; }
        #pragma unroll 4
        for (int y = 0; y < 64; y++) {
            float4 q4r = *(float4*)&qkr[y * 64 + x0];
            float4 q4i = *(float4*)&qki[y * 64 + x0];
            float qrv[4] = {q4r.x,q4r.y,q4r.z,q4r.w};
            float qiv[4] = {q4i.x,q4i.y,q4i.z,q4i.w};
            float krv[2], kiv[2];
            #pragma unroll
            for (int ee = 0; ee < 2; ee++) {
                krv[ee] = Ks[(e0 + ee) * 128 + y];
                kiv[ee] = Ks[(e0 + ee) * 128 + 64 + y];
            }
            #pragma unroll
            for (int ee = 0; ee < 2; ee++)
                #pragma unroll
                for (int xx = 0; xx < 4; xx++) {
                    cr[ee][xx] += qrv[xx]*krv[ee] - qiv[xx]*kiv[ee];
                    ci[ee][xx] += qrv[xx]*kiv[ee] + qiv[xx]*krv[ee];
                }
        }
        #pragma unroll
        for (int xx = 0; xx < 4; xx++) {
            size_t base = ((size_t)(h * 64 + x0 + xx) * 2) * 2048 + b * 64 + e0;
            *(float2*)&d_KV[base]        = make_float2(cr[0][xx], cr[1][xx]);
            *(float2*)&d_KV[base + 2048] = make_float2(ci[0][xx], ci[1][xx]);
        }
    }
}

// ---------------- stage4: per-(h,mode) pointwise complex GEMM --------------
__global__ __launch_bounds__(128) void xw_k() {
    extern __shared__ float sm[];
    float* kvS = sm;         // [e][c][b]
    float* wS  = sm + 4096;  // [e][c][o]
    const int x = blockIdx.x, h = blockIdx.y;
    const int tid = threadIdx.x;

    {
        const float4* kb = (const float4*)(d_KV + ((size_t)(h * 64 + x) * 2) * 2048);
        #pragma unroll
        for (int r = 0; r < 8; r++) {
            int idx4 = tid + 128 * r;
            float4 v = kb[idx4];
            int e4 = idx4 & 15, bb = (idx4 >> 4) & 31, c = idx4 >> 9;
            #pragma unroll
            for (int j = 0; j < 4; j++)
                kvS[((e4 * 4 + j) * 2 + c) * 32 + bb] = (&v.x)[j];
        }
        const float4* wrb = (const float4*)(d_WTr + (size_t)(h * 64 + x) * 4096);
        const float4* wib = (const float4*)(d_WTi + (size_t)(h * 64 + x) * 4096);
        #pragma unroll
        for (int r = 0; r < 8; r++) {
            int idx4 = tid + 128 * r;
            int e = idx4 >> 4, o4 = idx4 & 15;
            *(float4*)&wS[(e * 2 + 0) * 64 + o4 * 4] = wrb[idx4];
            *(float4*)&wS[(e * 2 + 1) * 64 + o4 * 4] = wib[idx4];
        }
    }
    __syncthreads();

    const int b0 = (tid >> 4) * 4;
    const int o0 = (tid & 15) * 4;
    float cr[4][4], ci[4][4];
    #pragma unroll
    for (int i = 0; i < 4; i++)
        #pragma unroll
        for (int j = 0; j < 4; j++) { cr[i][j] = 0.f; ci[i][j] = 0.f; }

    #pragma unroll 4
    for (int e = 0; e < 64; e++) {
        float4 kr4 = *(float4*)&kvS[(e * 2 + 0) * 32 + b0];
        float4 ki4 = *(float4*)&kvS[(e * 2 + 1) * 32 + b0];
        float4 wr4 = *(float4*)&wS[(e * 2 + 0) * 64 + o0];
        float4 wi4 = *(float4*)&wS[(e * 2 + 1) * 64 + o0];
        float kr[4] = {kr4.x,kr4.y,kr4.z,kr4.w};
        float ki[4] = {ki4.x,ki4.y,ki4.z,ki4.w};
        float wr[4] = {wr4.x,wr4.y,wr4.z,wr4.w};
        float wi[4] = {wi4.x,wi4.y,wi4.z,wi4.w};
        #pragma unroll
        for (int i = 0; i < 4; i++)
            #pragma unroll
            for (int j = 0; j < 4; j++) {
                cr[i][j] += kr[i]*wr[j] - ki[i]*wi[j];
                ci[i][j] += kr[i]*wi[j] + ki[i]*wr[j];
            }
    }
    __syncthreads();

    const float S = 1.0f / 262144.0f;
    #pragma unroll
    for (int i = 0; i < 4; i++) {
        *(float4*)&wS[(0 * 32 + b0 + i) * 64 + o0] =
            make_float4(cr[i][0]*S, cr[i][1]*S, cr[i][2]*S, cr[i][3]*S);
        *(float4*)&wS[(1 * 32 + b0 + i) * 64 + o0] =
            make_float4(ci[i][0]*S, ci[i][1]*S, ci[i][2]*S, ci[i][3]*S);
    }
    __syncthreads();

    int slot = d_pos2slot_q[x];
    #pragma unroll
    for (int r = 0; r < 8; r++) {
        int idx4 = tid + 128 * r;
        int c = idx4 >> 9, bb = (idx4 >> 4) & 31, o4 = idx4 & 15;
        *(float4*)&d_X2T[(size_t)(2 * slot + c) * 16384 + (bb * 8 + h) * 64 + o4 * 4] =
            ((float4*)wS)[idx4];
    }
}

// ---------------- inverse: radix-8 folded irfft -----------------------------
__global__ __launch_bounds__(256) void inv8_k(float* __restrict__ outp) {
    extern __shared__ float sm[];
    float* Ys = sm;              // [64 rows][128]
    float* Ar = sm + 8192;       // [64 slots][32 u]
    float* Ai = sm + 10240;
    float* Br = sm + 12288;
    float* Bi = sm + 14336;
    const int u0 = blockIdx.x * 32;
    const int r0 = blockIdx.y * 64;
    const int tid = threadIdx.x;

    for (int i = tid; i < 2048; i += 256) {
        int p = i >> 4, r4 = (i & 15) * 4;
        float4 v = *(const float4*)&d_X2T[(size_t)p * 16384 + r0 + r4];
        Ys[(r4 + 0) * 128 + p] = v.x;
        Ys[(r4 + 1) * 128 + p] = v.y;
        Ys[(r4 + 2) * 128 + p] = v.z;
        Ys[(r4 + 3) * 128 + p] = v.w;
    }
    for (int i = tid; i < 512; i += 256) {
        int s = i >> 3, f = (i & 7) * 4;
        *(float4*)&Ar[s * 32 + f] = *(const float4*)&d_IAr[s * 128 + u0 + f];
        *(float4*)&Ai[s * 32 + f] = *(const float4*)&d_IAi[s * 128 + u0 + f];
        *(float4*)&Br[s * 32 + f] = *(const float4*)&d_IBr[s * 128 + u0 + f];
        *(float4*)&Bi[s * 32 + f] = *(const float4*)&d_IBi[s * 128 + u0 + f];
    }
    __syncthreads();

    const int rr = (tid >> 4) * 4;
    const int uu = (tid & 15) * 2;
    float A0[4][2] = {}, A4[4][2] = {};
    float A1[4][2] = {}, B1[4][2] = {};
    float A2[4][2] = {}, B2[4][2] = {};
    float A3[4][2] = {}, B3[4][2] = {};

    const int n0 = d_bnd_q[0], n4 = d_bnd_q[1], n1 = d_bnd_q[2], n2 = d_bnd_q[3];

#define IACC_A(S, A) { \
    float2 a2 = *(float2*)&Ar[(S) * 32 + uu]; \
    float2 i2 = *(float2*)&Ai[(S) * 32 + uu]; \
    _Pragma("unroll") \
    for (int r_ = 0; r_ < 4; r_++) { \
        float2 y = *(float2*)&Ys[(rr + r_) * 128 + 2 * (S)]; \
        A[r_][0] += y.x * a2.x + y.y * i2.x; \
        A[r_][1] += y.x * a2.y + y.y * i2.y; \
    } }

#define IACC_AB(S, A, Bm) { \
    float2 a2 = *(float2*)&Ar[(S) * 32 + uu]; \
    float2 i2 = *(float2*)&Ai[(S) * 32 + uu]; \
    float2 b2 = *(float2*)&Br[(S) * 32 + uu]; \
    float2 c2 = *(float2*)&Bi[(S) * 32 + uu]; \
    _Pragma("unroll") \
    for (int r_ = 0; r_ < 4; r_++) { \
        float2 y = *(float2*)&Ys[(rr + r_) * 128 + 2 * (S)]; \
        A[r_][0]  += y.x * a2.x + y.y * i2.x; \
        A[r_][1]  += y.x * a2.y + y.y * i2.y; \
        Bm[r_][0] += y.x * b2.x + y.y * c2.x; \
        Bm[r_][1] += y.x * b2.y + y.y * c2.y; \
    } }

    for (int s = 0;  s < n0; s++) IACC_A(s, A0);
    for (int s = n0; s < n4; s++) IACC_A(s, A4);
    for (int s = n4; s < n1; s++) IACC_AB(s, A1, B1);
    for (int s = n1; s < n2; s++) IACC_AB(s, A2, B2);
    for (int s = n2; s < 64; s++) IACC_AB(s, A3, B3);

#undef IACC_A
#undef IACC_AB

    const float K = 0.70710678118654752440f;
    #pragma unroll
    for (int r_ = 0; r_ < 4; r_++) {
        float ov[8][2];
        #pragma unroll
        for (int u_ = 0; u_ < 2; u_++) {
            float a0 = A0[r_][u_], a4 = A4[r_][u_];
            float a1 = A1[r_][u_], b1 = B1[r_][u_];
            float a2 = A2[r_][u_], b2 = B2[r_][u_];
            float a3 = A3[r_][u_], b3 = B3[r_][u_];
            float pA = a0 + a4, mA = a0 - a4;
            float s1p = K * (a1 - b1), s1m = K * (a1 + b1);
            float s3p = K * (a3 + b3), s3m = K * (a3 - b3);
            ov[0][u_] = pA + a1 + a2 + a3;
            ov[1][u_] = mA + s1p - b2 - s3p;
            ov[2][u_] = pA - b1 - a2 + b3;
            ov[3][u_] = mA - s1m + b2 + s3m;
            ov[4][u_] = pA - a1 + a2 - a3;
            ov[5][u_] = mA - s1p - b2 + s3p;
            ov[6][u_] = pA + b1 - a2 - b3;
            ov[7][u_] = mA + s1m + b2 - s3m;
        }
        float* dst = outp + (size_t)(r0 + rr + r_) * L_ + u0 + uu;
        #pragma unroll
        for (int p = 0; p < 8; p++)
            *(float2*)(dst + 128 * p) = make_float2(ov[p][0], ov[p][1]);
    }
}

// ---------------- launch ---------------------------------------------------
extern "C" void kernel_launch(void* const* d_in, const int* in_sizes, int n_in,
                              void* d_out, int out_size) {
    const float* q   = (const float*)d_in[0];
    const float* k   = (const float*)d_in[1];
    const float* wr  = (const float*)d_in[4];
    const float* wi  = (const float*)d_in[5];
    const int*   iq  = (const int*)d_in[6];
    const int*   ikv = (const int*)d_in[7];
    float* out = (float*)d_out;

    setup1_k<<<7, 256>>>(iq, ikv);
    setup2_k<<<160, 256>>>();
    wtrans_k<<<dim3(4, 64, 8), 256>>>(wr, wi);
    cudaFuncSetAttribute(dft8m_k, cudaFuncAttributeMaxDynamicSharedMemorySize, 51200);
    dft8m_k<<<dim3(64, B_, 2), 128, 51200>>>(q, k);
    cudaFuncSetAttribute(stage23_k, cudaFuncAttributeMaxDynamicSharedMemorySize, 65536);
    stage23_k<<<dim3(H_, B_), 512, 65536>>>();
    cudaFuncSetAttribute(xw_k, cudaFuncAttributeMaxDynamicSharedMemorySize, 49152);
    xw_k<<<dim3(64, 8), 128, 49152>>>();
    cudaFuncSetAttribute(inv8_k, cudaFuncAttributeMaxDynamicSharedMemorySize, 65536);
    inv8_k<<<dim3(4, 256), 256, 65536>>>(out);
}